// round 5
// baseline (speedup 1.0000x reference)
#include <cuda_runtime.h>
#include <cuda_fp16.h>
#include <math.h>
#include <stdint.h>

#define IN_DIM 256
#define OUT_DIM 256
#define BATCH 2
#define MAXN 10240
#define MAXE 163840
#define SLOPE 0.2f

// ---------------- scratch (static device globals; no allocation) ----------
static __device__ float  g_src_proj[MAXN * BATCH * OUT_DIM];   // 20 MB
static __device__ __half g_vals_h[MAXN * BATCH * OUT_DIM];     // 10 MB
static __device__ float  g_sdot[MAXN * BATCH];
static __device__ float  g_tdot[MAXN * BATCH];
static __device__ float  g_ex[MAXE * BATCH];                   // alpha
static __device__ int    g_seg_start[MAXN];
static __device__ int    g_seg_end[MAXN];
static __device__ float  g_wta[IN_DIM];
static __device__ float  g_ct;
static __device__ int    g_idx64;

// ---------------- index dtype handling -------------------------------------
__device__ __forceinline__ int IDX(const void* p, int i, int is64) {
    if (is64) return (int)(((const long long*)p)[i]);
    return ((const int*)p)[i];
}

// ---------------- fused prep: detect + wta + ct -----------------------------
// grid = 33 blocks of 256. block 0: detect + ct. blocks 1..32: wta warp-per-k.
__global__ void k_prep(const void* __restrict__ usrc,
                       const float* __restrict__ Wt, const float* __restrict__ bt,
                       const float* __restrict__ Wa) {
    const int bid = blockIdx.x;
    const int t = threadIdx.x;
    if (bid == 0) {
        if (t == 0) {
            const int* p = (const int*)usrc;
            g_idx64 = (p[1] == 0 && p[3] == 0) ? 1 : 0;
        }
        __shared__ float red[256];
        red[t] = bt[t] * Wa[OUT_DIM + t];
        __syncthreads();
        for (int st = 128; st > 0; st >>= 1) {
            if (t < st) red[t] += red[t + st];
            __syncthreads();
        }
        if (t == 0) g_ct = red[0];
    } else {
        const int k = (bid - 1) * 8 + (t >> 5);
        const int lane = t & 31;
        const float* wrow = Wt + (long)k * OUT_DIM;
        float s = 0.f;
#pragma unroll
        for (int o = lane; o < OUT_DIM; o += 32) s = fmaf(wrow[o], Wa[OUT_DIM + o], s);
#pragma unroll
        for (int st = 16; st; st >>= 1) s += __shfl_xor_sync(0xFFFFFFFFu, s, st);
        if (lane == 0) g_wta[k] = s;
    }
}

// ---------------- tf32 mma.sync gathered GEMM (both GEMMs in one launch) ----
// z=0: g_src_proj = nodes[usrc gather] @ Ws + bs      (fp32 out)
// z=1: g_vals_h   = nodes[utgt gather] @ Wv + bv      (fp16 out)
#define AS_STRIDE 36
#define BS_STRIDE 136
#define AS_FLOATS (128 * AS_STRIDE)
#define BS_FLOATS (32 * BS_STRIDE)
#define SM_FLOATS (2 * AS_FLOATS + 2 * BS_FLOATS)

__device__ __forceinline__ uint32_t smem_u32(const void* p) {
    uint32_t a;
    asm("{ .reg .u64 t; cvta.to.shared.u64 t, %1; cvt.u32.u64 %0, t; }" : "=r"(a) : "l"(p));
    return a;
}
#define CP_ASYNC16(smaddr, gptr) \
    asm volatile("cp.async.ca.shared.global [%0], [%1], 16;" :: "r"(smaddr), "l"(gptr))
#define CP_COMMIT() asm volatile("cp.async.commit_group;" ::: "memory")
#define CP_WAIT1()  asm volatile("cp.async.wait_group 1;" ::: "memory")
#define CP_WAIT0()  asm volatile("cp.async.wait_group 0;" ::: "memory")

__device__ __forceinline__ void mma_tf32(float* c, const uint32_t* a, uint32_t b0, uint32_t b1) {
    asm volatile(
        "mma.sync.aligned.m16n8k8.row.col.f32.tf32.tf32.f32 "
        "{%0,%1,%2,%3}, {%4,%5,%6,%7}, {%8,%9}, {%0,%1,%2,%3};"
        : "+f"(c[0]), "+f"(c[1]), "+f"(c[2]), "+f"(c[3])
        : "r"(a[0]), "r"(a[1]), "r"(a[2]), "r"(a[3]), "r"(b0), "r"(b1));
}

__global__ __launch_bounds__(256) void k_gemm_mma(
    const float* __restrict__ nodes,
    const void* __restrict__ usrc, const void* __restrict__ utgt,
    const float* __restrict__ Ws, const float* __restrict__ Wv,
    const float* __restrict__ bs, const float* __restrict__ bv,
    int Ms, int Mt)
{
    extern __shared__ float sm[];
    const int which = blockIdx.z;
    const void* __restrict__ uidx = which ? utgt : usrc;
    const float* __restrict__ W = which ? Wv : Ws;
    const float* __restrict__ bias = which ? bv : bs;
    const int M = which ? Mt : Ms;

    const int t = threadIdx.x;
    const int tile_m = blockIdx.x * 128;
    const int tile_n = blockIdx.y * 128;
    if (tile_m >= M) return;
    const int is64 = g_idx64;

    const int ar  = t >> 1;
    const int akk = (t & 1) * 16;
    const int mclamp = min(tile_m + ar, M - 1);
    const long gath = (long)IDX(uidx, mclamp >> 1, is64) * BATCH + (mclamp & 1);
    const float* __restrict__ aptr = nodes + gath * IN_DIM + akk;
    const int bk = t >> 3;
    const int bn = (t & 7) * 16;
    const float* __restrict__ bptr = W + (long)bk * OUT_DIM + tile_n + bn;

    const uint32_t sb = smem_u32(sm);
    const uint32_t a_sm_base = sb + (ar * AS_STRIDE + akk) * 4;
    const uint32_t b_sm_base = sb + (2 * AS_FLOATS + bk * BS_STRIDE + bn) * 4;

    const int wid = t >> 5, lane = t & 31;
    const int g = lane >> 2, tg = lane & 3;
    const int wm = (wid >> 1) * 32;
    const int wn = (wid & 1) * 64;

    float acc[2][8][4];
#pragma unroll
    for (int i = 0; i < 2; i++)
#pragma unroll
        for (int j = 0; j < 8; j++)
#pragma unroll
            for (int q = 0; q < 4; q++) acc[i][j][q] = 0.f;

#pragma unroll
    for (int q = 0; q < 4; q++) CP_ASYNC16(a_sm_base + q * 16, aptr + q * 4);
#pragma unroll
    for (int q = 0; q < 4; q++) CP_ASYNC16(b_sm_base + q * 16, bptr + q * 4);
    CP_COMMIT();

    for (int c = 0; c < 8; c++) {
        const int buf = c & 1;
        if (c < 7) {
            const int kb = (c + 1) * 32;
            const uint32_t abuf = a_sm_base + (buf ^ 1) * (AS_FLOATS * 4);
            const uint32_t bbuf = b_sm_base + (buf ^ 1) * (BS_FLOATS * 4);
#pragma unroll
            for (int q = 0; q < 4; q++) CP_ASYNC16(abuf + q * 16, aptr + kb + q * 4);
#pragma unroll
            for (int q = 0; q < 4; q++) CP_ASYNC16(bbuf + q * 16, bptr + (long)kb * OUT_DIM + q * 4);
            CP_COMMIT();
            CP_WAIT1();
        } else {
            CP_WAIT0();
        }
        __syncthreads();

        const float* __restrict__ A = sm + buf * AS_FLOATS;
        const float* __restrict__ B = sm + 2 * AS_FLOATS + buf * BS_FLOATS;
#pragma unroll
        for (int k0 = 0; k0 < 32; k0 += 8) {
            uint32_t a0[4], a1[4];
            a0[0] = __float_as_uint(A[(wm + g)      * AS_STRIDE + k0 + tg]);
            a0[1] = __float_as_uint(A[(wm + g + 8)  * AS_STRIDE + k0 + tg]);
            a0[2] = __float_as_uint(A[(wm + g)      * AS_STRIDE + k0 + tg + 4]);
            a0[3] = __float_as_uint(A[(wm + g + 8)  * AS_STRIDE + k0 + tg + 4]);
            a1[0] = __float_as_uint(A[(wm + 16 + g)     * AS_STRIDE + k0 + tg]);
            a1[1] = __float_as_uint(A[(wm + 16 + g + 8) * AS_STRIDE + k0 + tg]);
            a1[2] = __float_as_uint(A[(wm + 16 + g)     * AS_STRIDE + k0 + tg + 4]);
            a1[3] = __float_as_uint(A[(wm + 16 + g + 8) * AS_STRIDE + k0 + tg + 4]);
#pragma unroll
            for (int bx = 0; bx < 8; bx++) {
                uint32_t b0 = __float_as_uint(B[(k0 + tg)     * BS_STRIDE + wn + bx * 8 + g]);
                uint32_t b1 = __float_as_uint(B[(k0 + tg + 4) * BS_STRIDE + wn + bx * 8 + g]);
                mma_tf32(acc[0][bx], a0, b0, b1);
                mma_tf32(acc[1][bx], a1, b0, b1);
            }
        }
        __syncthreads();
    }

    // ---- epilogue ----
#pragma unroll
    for (int am = 0; am < 2; am++) {
        const int m0 = tile_m + wm + am * 16 + g;
        const int m1 = m0 + 8;
#pragma unroll
        for (int bx = 0; bx < 8; bx++) {
            const int col = tile_n + wn + bx * 8 + tg * 2;
            const float bi0 = bias[col], bi1 = bias[col + 1];
            if (which == 0) {
                if (m0 < M) {
                    float2 v = make_float2(acc[am][bx][0] + bi0, acc[am][bx][1] + bi1);
                    *reinterpret_cast<float2*>(g_src_proj + (long)m0 * OUT_DIM + col) = v;
                }
                if (m1 < M) {
                    float2 v = make_float2(acc[am][bx][2] + bi0, acc[am][bx][3] + bi1);
                    *reinterpret_cast<float2*>(g_src_proj + (long)m1 * OUT_DIM + col) = v;
                }
            } else {
                if (m0 < M) {
                    __half2 h = __floats2half2_rn(acc[am][bx][0] + bi0, acc[am][bx][1] + bi1);
                    *reinterpret_cast<__half2*>(g_vals_h + (long)m0 * OUT_DIM + col) = h;
                }
                if (m1 < M) {
                    __half2 h = __floats2half2_rn(acc[am][bx][2] + bi0, acc[am][bx][3] + bi1);
                    *reinterpret_cast<__half2*>(g_vals_h + (long)m1 * OUT_DIM + col) = h;
                }
            }
        }
    }
}

// ---------------- merged sdot/tdot (warp per row) ---------------------------
__global__ void k_dots(const float* __restrict__ nodes, const void* __restrict__ utgt,
                       const float* __restrict__ Wa, int Ms, int Mt) {
    int w = (blockIdx.x * blockDim.x + threadIdx.x) >> 5;
    int lane = threadIdx.x & 31;
    if (w < Ms) {
        const float* row = g_src_proj + (long)w * OUT_DIM;
        float s = 0.f;
#pragma unroll
        for (int o = lane; o < OUT_DIM; o += 32) s = fmaf(row[o], Wa[o], s);
#pragma unroll
        for (int st = 16; st; st >>= 1) s += __shfl_xor_sync(0xFFFFFFFFu, s, st);
        if (lane == 0) g_sdot[w] = s;
    } else if (w < Ms + Mt) {
        int m = w - Ms;
        int is64 = g_idx64;
        int nidx = m >> 1, b = m & 1;
        long gidx = (long)IDX(utgt, nidx, is64) * BATCH + b;
        const float* row = nodes + gidx * IN_DIM;
        float s = 0.f;
#pragma unroll
        for (int o = lane; o < IN_DIM; o += 32) s = fmaf(row[o], g_wta[o], s);
#pragma unroll
        for (int st = 16; st; st >>= 1) s += __shfl_xor_sync(0xFFFFFFFFu, s, st);
        if (lane == 0) g_tdot[m] = s + g_ct;
    }
}

// ---------------- fused softmax: warp per source node -----------------------
// sid is sorted (edges sorted by source): binary-search segment, compute
// ex = exp(clip(leaky(score))), warp-reduce denom, store alpha and seg bounds.
__global__ void k_softmax(const void* __restrict__ sidp, const void* __restrict__ tidp,
                          const float* __restrict__ ba, int Ns, int E) {
    const int w = (blockIdx.x * blockDim.x + threadIdx.x) >> 5;
    const int lane = threadIdx.x & 31;
    if (w >= Ns) return;
    const int is64 = g_idx64;

    int res = 0;
    if (lane < 2) {
        int target = w + lane;
        int lo = 0, hi = E;
        while (lo < hi) {
            int mid = (lo + hi) >> 1;
            if (IDX(sidp, mid, is64) < target) lo = mid + 1; else hi = mid;
        }
        res = lo;
    }
    const int s0 = __shfl_sync(0xFFFFFFFFu, res, 0);
    const int s1 = __shfl_sync(0xFFFFFFFFu, res, 1);
    if (lane == 0) { g_seg_start[w] = s0; g_seg_end[w] = s1; }

    const float b0 = ba[0];
    const float sd0 = g_sdot[w * 2 + 0];
    const float sd1 = g_sdot[w * 2 + 1];

    float d0 = 0.f, d1 = 0.f;
    for (int e = s0 + lane; e < s1; e += 32) {
        int tg = IDX(tidp, e, is64);
        float sc0 = sd0 + g_tdot[tg * 2 + 0] + b0;
        float sc1 = sd1 + g_tdot[tg * 2 + 1] + b0;
        sc0 = (sc0 >= 0.f) ? sc0 : SLOPE * sc0;
        sc1 = (sc1 >= 0.f) ? sc1 : SLOPE * sc1;
        sc0 = fminf(2.f, fmaxf(-2.f, sc0));
        sc1 = fminf(2.f, fmaxf(-2.f, sc1));
        float e0 = expf(sc0), e1 = expf(sc1);
        g_ex[e * 2 + 0] = e0;
        g_ex[e * 2 + 1] = e1;
        d0 += e0;
        d1 += e1;
    }
#pragma unroll
    for (int st = 16; st; st >>= 1) {
        d0 += __shfl_xor_sync(0xFFFFFFFFu, d0, st);
        d1 += __shfl_xor_sync(0xFFFFFFFFu, d1, st);
    }
    const float inv0 = 1.f / d0, inv1 = 1.f / d1;
    for (int e = s0 + lane; e < s1; e += 32) {
        g_ex[e * 2 + 0] *= inv0;
        g_ex[e * 2 + 1] *= inv1;
    }
}

// ---------------- aggregation (fp16 vals, fp32 accumulate) ------------------
// out[n,b,:] = src_proj[n,b,:] + sum_{e in seg(n)} alpha[tid[e],b] * vals[tid[tid[e]],b,:]
__global__ __launch_bounds__(512) void k_agg(const void* __restrict__ tidp,
                                             float* __restrict__ out, int Ns) {
    __shared__ float ws[2][32];
    __shared__ int rows[32];
    const int n = blockIdx.x;
    const int t = threadIdx.x;
    const int b = t >> 8;
    const int o = t & 255;
    const int is64 = g_idx64;
    const int s0 = g_seg_start[n], s1 = g_seg_end[n];
    const long outrow = ((long)n * BATCH + b) * OUT_DIM + o;
    float accA = g_src_proj[outrow];
    float accB = 0.f;
    for (int base = s0; base < s1; base += 32) {
        int cnt = min(32, s1 - base);
        if (t < cnt) {
            int j = IDX(tidp, base + t, is64);
            ws[0][t] = g_ex[j * 2 + 0];
            ws[1][t] = g_ex[j * 2 + 1];
            rows[t] = IDX(tidp, j, is64);
        }
        __syncthreads();
        int i = 0;
        for (; i + 2 <= cnt; i += 2) {
            int r0 = rows[i], r1 = rows[i + 1];
            float v0 = __half2float(g_vals_h[(((long)r0 << 1) + b) * OUT_DIM + o]);
            float v1 = __half2float(g_vals_h[(((long)r1 << 1) + b) * OUT_DIM + o]);
            accA = fmaf(ws[b][i],     v0, accA);
            accB = fmaf(ws[b][i + 1], v1, accB);
        }
        if (i < cnt) {
            int r = rows[i];
            float v = __half2float(g_vals_h[(((long)r << 1) + b) * OUT_DIM + o]);
            accA = fmaf(ws[b][i], v, accA);
        }
        __syncthreads();
    }
    out[outrow] = accA + accB;
}

extern "C" void kernel_launch(void* const* d_in, const int* in_sizes, int n_in,
                              void* d_out, int out_size) {
    const float* nodes = (const float*)d_in[0];
    const float* Ws    = (const float*)d_in[1];
    const float* bs    = (const float*)d_in[2];
    const float* Wt    = (const float*)d_in[3];
    const float* bt    = (const float*)d_in[4];
    const float* Wv    = (const float*)d_in[5];
    const float* bv    = (const float*)d_in[6];
    const float* Wa    = (const float*)d_in[7];
    const float* ba    = (const float*)d_in[8];
    const void* usrc   = d_in[9];
    const void* utgt   = d_in[10];
    const void* sidp   = d_in[11];
    const void* tidp   = d_in[12];

    const int Ns = in_sizes[9];
    const int Nt = in_sizes[10];
    const int E  = in_sizes[11];
    float* out = (float*)d_out;

    static int smem_set = 0;
    if (!smem_set) {
        cudaFuncSetAttribute(k_gemm_mma, cudaFuncAttributeMaxDynamicSharedMemorySize,
                             SM_FLOATS * 4);
        smem_set = 1;
    }

    const int Ms = Ns * BATCH;
    const int Mt = Nt * BATCH;

    k_prep<<<33, 256>>>(usrc, Wt, bt, Wa);

    const int Mmax = (Ms > Mt) ? Ms : Mt;
    dim3 gg((Mmax + 127) / 128, OUT_DIM / 128, 2);
    k_gemm_mma<<<gg, 256, SM_FLOATS * 4>>>(nodes, usrc, utgt, Ws, Wv, bs, bv, Ms, Mt);

    k_dots<<<((Ms + Mt) * 32 + 255) / 256, 256>>>(nodes, utgt, Wa, Ms, Mt);

    k_softmax<<<(Ns + 7) / 8, 256>>>(sidp, tidp, ba, Ns, E);

    k_agg<<<Ns, 512>>>(tidp, out, Ns);
}

// round 7
// speedup vs baseline: 1.0378x; 1.0378x over previous
#include <cuda_runtime.h>
#include <cuda_fp16.h>
#include <math.h>
#include <stdint.h>

#define IN_DIM 256
#define OUT_DIM 256
#define BATCH 2
#define MAXN 10240
#define MAXE 163840
#define SLOPE 0.2f

// ---------------- scratch (static device globals; no allocation) ----------
static __device__ float  g_src_proj[MAXN * BATCH * OUT_DIM];    // 20 MB
static __device__ __half g_vals_h[MAXN * BATCH * OUT_DIM];      // 10 MB
static __device__ float  g_sdot_part[4][MAXN * BATCH];          // partial dots
static __device__ float  g_tdot[MAXN * BATCH];
static __device__ float  g_denom[MAXN * BATCH];
static __device__ float  g_ex[MAXE * BATCH];
static __device__ float2 g_w[MAXE];                             // packed weights
static __device__ int    g_row[MAXE];                           // packed rows
static __device__ int    g_seg_start[MAXN];
static __device__ int    g_seg_end[MAXN];
static __device__ float  g_wta[IN_DIM];
static __device__ float  g_ct;
static __device__ int    g_idx64;

// ---------------- index dtype handling -------------------------------------
__device__ __forceinline__ int IDX(const void* p, int i, int is64) {
    if (is64) return (int)(((const long long*)p)[i]);
    return ((const int*)p)[i];
}

// ---------------- fused prep: detect + wta + ct -----------------------------
__global__ void k_prep(const void* __restrict__ usrc,
                       const float* __restrict__ Wt, const float* __restrict__ bt,
                       const float* __restrict__ Wa) {
    const int bid = blockIdx.x;
    const int t = threadIdx.x;
    if (bid == 0) {
        if (t == 0) {
            const int* p = (const int*)usrc;
            g_idx64 = (p[1] == 0 && p[3] == 0) ? 1 : 0;
        }
        __shared__ float red[256];
        red[t] = bt[t] * Wa[OUT_DIM + t];
        __syncthreads();
        for (int st = 128; st > 0; st >>= 1) {
            if (t < st) red[t] += red[t + st];
            __syncthreads();
        }
        if (t == 0) g_ct = red[0];
    } else {
        const int k = (bid - 1) * 8 + (t >> 5);
        const int lane = t & 31;
        const float* wrow = Wt + (long)k * OUT_DIM;
        float s = 0.f;
#pragma unroll
        for (int o = lane; o < OUT_DIM; o += 32) s = fmaf(wrow[o], Wa[OUT_DIM + o], s);
#pragma unroll
        for (int st = 16; st; st >>= 1) s += __shfl_xor_sync(0xFFFFFFFFu, s, st);
        if (lane == 0) g_wta[k] = s;
    }
}

// ---------------- tdot (warp per row) ---------------------------------------
__global__ void k_tdot(const float* __restrict__ nodes, const void* __restrict__ utgt,
                       int Mt) {
    int m = (blockIdx.x * blockDim.x + threadIdx.x) >> 5;
    int lane = threadIdx.x & 31;
    if (m >= Mt) return;
    int is64 = g_idx64;
    int nidx = m >> 1, b = m & 1;
    long gidx = (long)IDX(utgt, nidx, is64) * BATCH + b;
    const float* row = nodes + gidx * IN_DIM;
    float s = 0.f;
#pragma unroll
    for (int o = lane; o < IN_DIM; o += 32) s = fmaf(row[o], g_wta[o], s);
#pragma unroll
    for (int st = 16; st; st >>= 1) s += __shfl_xor_sync(0xFFFFFFFFu, s, st);
    if (lane == 0) g_tdot[m] = s + g_ct;
}

// ---------------- tf32 mma.sync gathered GEMM -------------------------------
// z=0: g_src_proj = nodes[usrc] @ Ws + bs (fp32) + sdot partials fused
// z=1: g_vals_h   = nodes[utgt] @ Wv + bv (fp16)
#define AS_STRIDE 36
#define BS_STRIDE 136
#define AS_FLOATS (128 * AS_STRIDE)
#define BS_FLOATS (32 * BS_STRIDE)
#define SM_FLOATS (2 * AS_FLOATS + 2 * BS_FLOATS)

__device__ __forceinline__ uint32_t smem_u32(const void* p) {
    uint32_t a;
    asm("{ .reg .u64 t; cvta.to.shared.u64 t, %1; cvt.u32.u64 %0, t; }" : "=r"(a) : "l"(p));
    return a;
}
#define CP_ASYNC16(smaddr, gptr) \
    asm volatile("cp.async.ca.shared.global [%0], [%1], 16;" :: "r"(smaddr), "l"(gptr))
#define CP_COMMIT() asm volatile("cp.async.commit_group;" ::: "memory")
#define CP_WAIT1()  asm volatile("cp.async.wait_group 1;" ::: "memory")
#define CP_WAIT0()  asm volatile("cp.async.wait_group 0;" ::: "memory")

__device__ __forceinline__ void mma_tf32(float* c, const uint32_t* a, uint32_t b0, uint32_t b1) {
    asm volatile(
        "mma.sync.aligned.m16n8k8.row.col.f32.tf32.tf32.f32 "
        "{%0,%1,%2,%3}, {%4,%5,%6,%7}, {%8,%9}, {%0,%1,%2,%3};"
        : "+f"(c[0]), "+f"(c[1]), "+f"(c[2]), "+f"(c[3])
        : "r"(a[0]), "r"(a[1]), "r"(a[2]), "r"(a[3]), "r"(b0), "r"(b1));
}

__global__ __launch_bounds__(256) void k_gemm_mma(
    const float* __restrict__ nodes,
    const void* __restrict__ usrc, const void* __restrict__ utgt,
    const float* __restrict__ Ws, const float* __restrict__ Wv,
    const float* __restrict__ bs, const float* __restrict__ bv,
    const float* __restrict__ Wa, int Ms, int Mt)
{
    extern __shared__ float sm[];
    const int which = blockIdx.z;
    const void* __restrict__ uidx = which ? utgt : usrc;
    const float* __restrict__ W = which ? Wv : Ws;
    const float* __restrict__ bias = which ? bv : bs;
    const int M = which ? Mt : Ms;

    const int t = threadIdx.x;
    const int tile_m = blockIdx.x * 128;
    const int tile_n = blockIdx.y * 128;
    if (tile_m >= M) return;
    const int is64 = g_idx64;

    const int ar  = t >> 1;
    const int akk = (t & 1) * 16;
    const int mclamp = min(tile_m + ar, M - 1);
    const long gath = (long)IDX(uidx, mclamp >> 1, is64) * BATCH + (mclamp & 1);
    const float* __restrict__ aptr = nodes + gath * IN_DIM + akk;
    const int bk = t >> 3;
    const int bn = (t & 7) * 16;
    const float* __restrict__ bptr = W + (long)bk * OUT_DIM + tile_n + bn;

    const uint32_t sb = smem_u32(sm);
    const uint32_t a_sm_base = sb + (ar * AS_STRIDE + akk) * 4;
    const uint32_t b_sm_base = sb + (2 * AS_FLOATS + bk * BS_STRIDE + bn) * 4;

    const int wid = t >> 5, lane = t & 31;
    const int g = lane >> 2, tg = lane & 3;
    const int wm = (wid >> 1) * 32;
    const int wn = (wid & 1) * 64;

    float acc[2][8][4];
#pragma unroll
    for (int i = 0; i < 2; i++)
#pragma unroll
        for (int j = 0; j < 8; j++)
#pragma unroll
            for (int q = 0; q < 4; q++) acc[i][j][q] = 0.f;

#pragma unroll
    for (int q = 0; q < 4; q++) CP_ASYNC16(a_sm_base + q * 16, aptr + q * 4);
#pragma unroll
    for (int q = 0; q < 4; q++) CP_ASYNC16(b_sm_base + q * 16, bptr + q * 4);
    CP_COMMIT();

    for (int c = 0; c < 8; c++) {
        const int buf = c & 1;
        if (c < 7) {
            const int kb = (c + 1) * 32;
            const uint32_t abuf = a_sm_base + (buf ^ 1) * (AS_FLOATS * 4);
            const uint32_t bbuf = b_sm_base + (buf ^ 1) * (BS_FLOATS * 4);
#pragma unroll
            for (int q = 0; q < 4; q++) CP_ASYNC16(abuf + q * 16, aptr + kb + q * 4);
#pragma unroll
            for (int q = 0; q < 4; q++) CP_ASYNC16(bbuf + q * 16, bptr + (long)kb * OUT_DIM + q * 4);
            CP_COMMIT();
            CP_WAIT1();
        } else {
            CP_WAIT0();
        }
        __syncthreads();

        const float* __restrict__ A = sm + buf * AS_FLOATS;
        const float* __restrict__ B = sm + 2 * AS_FLOATS + buf * BS_FLOATS;
#pragma unroll
        for (int k0 = 0; k0 < 32; k0 += 8) {
            uint32_t a0[4], a1[4];
            a0[0] = __float_as_uint(A[(wm + g)      * AS_STRIDE + k0 + tg]);
            a0[1] = __float_as_uint(A[(wm + g + 8)  * AS_STRIDE + k0 + tg]);
            a0[2] = __float_as_uint(A[(wm + g)      * AS_STRIDE + k0 + tg + 4]);
            a0[3] = __float_as_uint(A[(wm + g + 8)  * AS_STRIDE + k0 + tg + 4]);
            a1[0] = __float_as_uint(A[(wm + 16 + g)     * AS_STRIDE + k0 + tg]);
            a1[1] = __float_as_uint(A[(wm + 16 + g + 8) * AS_STRIDE + k0 + tg]);
            a1[2] = __float_as_uint(A[(wm + 16 + g)     * AS_STRIDE + k0 + tg + 4]);
            a1[3] = __float_as_uint(A[(wm + 16 + g + 8) * AS_STRIDE + k0 + tg + 4]);
#pragma unroll
            for (int bx = 0; bx < 8; bx++) {
                uint32_t b0 = __float_as_uint(B[(k0 + tg)     * BS_STRIDE + wn + bx * 8 + g]);
                uint32_t b1 = __float_as_uint(B[(k0 + tg + 4) * BS_STRIDE + wn + bx * 8 + g]);
                mma_tf32(acc[0][bx], a0, b0, b1);
                mma_tf32(acc[1][bx], a1, b0, b1);
            }
        }
        __syncthreads();
    }

    // ---- epilogue ----
    const int slot = blockIdx.y * 2 + (wid & 1);
#pragma unroll
    for (int am = 0; am < 2; am++) {
        const int m0 = tile_m + wm + am * 16 + g;
        const int m1 = m0 + 8;
        float d0 = 0.f, d1 = 0.f;
#pragma unroll
        for (int bx = 0; bx < 8; bx++) {
            const int col = tile_n + wn + bx * 8 + tg * 2;
            const float bi0 = bias[col], bi1 = bias[col + 1];
            float v00 = acc[am][bx][0] + bi0, v01 = acc[am][bx][1] + bi1;
            float v10 = acc[am][bx][2] + bi0, v11 = acc[am][bx][3] + bi1;
            if (which == 0) {
                const float wa0 = Wa[col], wa1 = Wa[col + 1];
                d0 = fmaf(v00, wa0, fmaf(v01, wa1, d0));
                d1 = fmaf(v10, wa0, fmaf(v11, wa1, d1));
                if (m0 < M)
                    *reinterpret_cast<float2*>(g_src_proj + (long)m0 * OUT_DIM + col) =
                        make_float2(v00, v01);
                if (m1 < M)
                    *reinterpret_cast<float2*>(g_src_proj + (long)m1 * OUT_DIM + col) =
                        make_float2(v10, v11);
            } else {
                if (m0 < M)
                    *reinterpret_cast<__half2*>(g_vals_h + (long)m0 * OUT_DIM + col) =
                        __floats2half2_rn(v00, v01);
                if (m1 < M)
                    *reinterpret_cast<__half2*>(g_vals_h + (long)m1 * OUT_DIM + col) =
                        __floats2half2_rn(v10, v11);
            }
        }
        if (which == 0) {
            // reduce across tg (lanes differing in bits 0..1)
            d0 += __shfl_xor_sync(0xFFFFFFFFu, d0, 1);
            d0 += __shfl_xor_sync(0xFFFFFFFFu, d0, 2);
            d1 += __shfl_xor_sync(0xFFFFFFFFu, d1, 1);
            d1 += __shfl_xor_sync(0xFFFFFFFFu, d1, 2);
            if (tg == 0) {
                if (m0 < M) g_sdot_part[slot][m0] = d0;
                if (m1 < M) g_sdot_part[slot][m1] = d1;
            }
        }
    }
}

// ---------------- edge: ex + segment bounds (sorted sid) --------------------
__global__ void k_edge(const void* __restrict__ sidp, const void* __restrict__ tidp,
                       const float* __restrict__ ba, int E) {
    int e = blockIdx.x * blockDim.x + threadIdx.x;
    if (e >= E) return;
    const int is64 = g_idx64;
    const int s = IDX(sidp, e, is64);
    if (e == 0 || IDX(sidp, e - 1, is64) != s) g_seg_start[s] = e;
    if (e == E - 1 || IDX(sidp, e + 1, is64) != s) g_seg_end[s] = e + 1;
    const int tg = IDX(tidp, e, is64);
    const float b0 = ba[0];
#pragma unroll
    for (int b = 0; b < BATCH; b++) {
        float sd = g_sdot_part[0][s * 2 + b] + g_sdot_part[1][s * 2 + b]
                 + g_sdot_part[2][s * 2 + b] + g_sdot_part[3][s * 2 + b];
        float sc = sd + g_tdot[tg * 2 + b] + b0;
        sc = (sc >= 0.f) ? sc : SLOPE * sc;
        sc = fminf(2.f, fmaxf(-2.f, sc));
        g_ex[e * 2 + b] = expf(sc);
    }
}

// deterministic segment-sum of ex
__global__ void k_denom(int Ns) {
    int i = blockIdx.x * blockDim.x + threadIdx.x;
    if (i >= Ns * BATCH) return;
    int n = i >> 1, b = i & 1;
    int s0 = g_seg_start[n], s1 = g_seg_end[n];
    float d = 0.f;
    for (int e = s0; e < s1; e++) d += g_ex[e * 2 + b];
    g_denom[i] = d;
}

// pack per-edge: w = alpha[tid[e]], row = tid[tid[e]]
__global__ void k_pack(const void* __restrict__ sidp, const void* __restrict__ tidp,
                       int E) {
    int e = blockIdx.x * blockDim.x + threadIdx.x;
    if (e >= E) return;
    const int is64 = g_idx64;
    const int j = IDX(tidp, e, is64);       // edge index (faithful bug)
    const int sj = IDX(sidp, j, is64);
    float w0 = g_ex[j * 2 + 0] / g_denom[sj * 2 + 0];
    float w1 = g_ex[j * 2 + 1] / g_denom[sj * 2 + 1];
    g_w[e] = make_float2(w0, w1);
    g_row[e] = IDX(tidp, j, is64);
}

// ---------------- aggregation (packed stream, unrolled MLP) -----------------
__global__ __launch_bounds__(512) void k_agg(float* __restrict__ out, int Ns) {
    __shared__ float2 ws[32];
    __shared__ int rs[32];
    const int n = blockIdx.x;
    const int t = threadIdx.x;
    const int b = t >> 8;
    const int o = t & 255;
    const int s0 = g_seg_start[n], s1 = g_seg_end[n];
    const int cnt = s1 - s0;
    const long outrow = ((long)n * BATCH + b) * OUT_DIM + o;
    float a0 = g_src_proj[outrow], a1 = 0.f, a2 = 0.f, a3 = 0.f;

    if (cnt == 16) {
        if (t < 16) { ws[t] = g_w[s0 + t]; rs[t] = g_row[s0 + t]; }
        __syncthreads();
        float w[16], v[16];
#pragma unroll
        for (int i = 0; i < 16; i++) {
            w[i] = b ? ws[i].y : ws[i].x;
            v[i] = __half2float(g_vals_h[(((long)rs[i] << 1) + b) * OUT_DIM + o]);
        }
#pragma unroll
        for (int i = 0; i < 16; i += 4) {
            a0 = fmaf(w[i],     v[i],     a0);
            a1 = fmaf(w[i + 1], v[i + 1], a1);
            a2 = fmaf(w[i + 2], v[i + 2], a2);
            a3 = fmaf(w[i + 3], v[i + 3], a3);
        }
    } else {
        for (int base = s0; base < s1; base += 32) {
            int c = min(32, s1 - base);
            if (t < c) { ws[t] = g_w[base + t]; rs[t] = g_row[base + t]; }
            __syncthreads();
            for (int i = 0; i < c; i++) {
                float w = b ? ws[i].y : ws[i].x;
                float v = __half2float(g_vals_h[(((long)rs[i] << 1) + b) * OUT_DIM + o]);
                a0 = fmaf(w, v, a0);
            }
            __syncthreads();
        }
    }
    out[outrow] = (a0 + a1) + (a2 + a3);
}

extern "C" void kernel_launch(void* const* d_in, const int* in_sizes, int n_in,
                              void* d_out, int out_size) {
    const float* nodes = (const float*)d_in[0];
    const float* Ws    = (const float*)d_in[1];
    const float* bs    = (const float*)d_in[2];
    const float* Wt    = (const float*)d_in[3];
    const float* bt    = (const float*)d_in[4];
    const float* Wv    = (const float*)d_in[5];
    const float* bv    = (const float*)d_in[6];
    const float* Wa    = (const float*)d_in[7];
    const float* ba    = (const float*)d_in[8];
    const void* usrc   = d_in[9];
    const void* utgt   = d_in[10];
    const void* sidp   = d_in[11];
    const void* tidp   = d_in[12];

    const int Ns = in_sizes[9];
    const int Nt = in_sizes[10];
    const int E  = in_sizes[11];
    float* out = (float*)d_out;

    static int smem_set = 0;
    if (!smem_set) {
        cudaFuncSetAttribute(k_gemm_mma, cudaFuncAttributeMaxDynamicSharedMemorySize,
                             SM_FLOATS * 4);
        smem_set = 1;
    }

    const int Ms = Ns * BATCH;
    const int Mt = Nt * BATCH;

    k_prep<<<33, 256>>>(usrc, Wt, bt, Wa);
    k_tdot<<<(Mt * 32 + 255) / 256, 256>>>(nodes, utgt, Mt);

    const int Mmax = (Ms > Mt) ? Ms : Mt;
    dim3 gg((Mmax + 127) / 128, OUT_DIM / 128, 2);
    k_gemm_mma<<<gg, 256, SM_FLOATS * 4>>>(nodes, usrc, utgt, Ws, Wv, bs, bv, Wa, Ms, Mt);

    k_edge<<<(E + 255) / 256, 256>>>(sidp, tidp, ba, E);
    k_denom<<<(Ns * BATCH + 255) / 256, 256>>>(Ns);
    k_pack<<<(E + 255) / 256, 256>>>(sidp, tidp, E);

    k_agg<<<Ns, 512>>>(out, Ns);
}

// round 8
// speedup vs baseline: 1.1419x; 1.1004x over previous
#include <cuda_runtime.h>
#include <cuda_fp16.h>
#include <math.h>
#include <stdint.h>

#define IN_DIM 256
#define OUT_DIM 256
#define BATCH 2
#define MAXN 10240
#define MAXE 163840
#define SLOPE 0.2f

// ---------------- scratch (static device globals; no allocation) ----------
static __device__ float  g_src_proj[MAXN * BATCH * OUT_DIM];    // 20 MB
static __device__ __half g_vals_h[MAXN * BATCH * OUT_DIM];      // 10 MB
static __device__ float  g_sdot_part[8][MAXN * BATCH];          // partial dots
static __device__ float  g_tdot[MAXN * BATCH];
static __device__ float  g_denom[MAXN * BATCH];
static __device__ float  g_ex[MAXE * BATCH];
static __device__ float2 g_w[MAXE];                             // packed weights
static __device__ int    g_row[MAXE];                           // packed rows
static __device__ int    g_seg_start[MAXN];
static __device__ int    g_seg_end[MAXN];
static __device__ float  g_wta[IN_DIM];
static __device__ float  g_ct;
static __device__ int    g_idx64;

// ---------------- index dtype handling -------------------------------------
__device__ __forceinline__ int IDX(const void* p, int i, int is64) {
    if (is64) return (int)(((const long long*)p)[i]);
    return ((const int*)p)[i];
}

// ---------------- fused prep: detect + wta + ct -----------------------------
__global__ void k_prep(const void* __restrict__ usrc,
                       const float* __restrict__ Wt, const float* __restrict__ bt,
                       const float* __restrict__ Wa) {
    const int bid = blockIdx.x;
    const int t = threadIdx.x;
    if (bid == 0) {
        if (t == 0) {
            const int* p = (const int*)usrc;
            g_idx64 = (p[1] == 0 && p[3] == 0) ? 1 : 0;
        }
        __shared__ float red[256];
        red[t] = bt[t] * Wa[OUT_DIM + t];
        __syncthreads();
        for (int st = 128; st > 0; st >>= 1) {
            if (t < st) red[t] += red[t + st];
            __syncthreads();
        }
        if (t == 0) g_ct = red[0];
    } else {
        const int k = (bid - 1) * 8 + (t >> 5);
        const int lane = t & 31;
        const float* wrow = Wt + (long)k * OUT_DIM;
        float s = 0.f;
#pragma unroll
        for (int o = lane; o < OUT_DIM; o += 32) s = fmaf(wrow[o], Wa[OUT_DIM + o], s);
#pragma unroll
        for (int st = 16; st; st >>= 1) s += __shfl_xor_sync(0xFFFFFFFFu, s, st);
        if (lane == 0) g_wta[k] = s;
    }
}

// ---------------- tdot (warp per row) ---------------------------------------
__global__ void k_tdot(const float* __restrict__ nodes, const void* __restrict__ utgt,
                       int Mt) {
    int m = (blockIdx.x * blockDim.x + threadIdx.x) >> 5;
    int lane = threadIdx.x & 31;
    if (m >= Mt) return;
    int is64 = g_idx64;
    int nidx = m >> 1, b = m & 1;
    long gidx = (long)IDX(utgt, nidx, is64) * BATCH + b;
    const float* row = nodes + gidx * IN_DIM;
    float s = 0.f;
#pragma unroll
    for (int o = lane; o < IN_DIM; o += 32) s = fmaf(row[o], g_wta[o], s);
#pragma unroll
    for (int st = 16; st; st >>= 1) s += __shfl_xor_sync(0xFFFFFFFFu, s, st);
    if (lane == 0) g_tdot[m] = s + g_ct;
}

// ---------------- tf32 mma.sync gathered GEMM (512 threads, 16 warps) -------
// z=0: g_src_proj = nodes[usrc] @ Ws + bs (fp32) + sdot partials fused
// z=1: g_vals_h   = nodes[utgt] @ Wv + bv (fp16)
// CTA tile 128x128, K chunk 32, warp tile 32x32 (4x4 warp grid).
#define AS_STRIDE 36
#define BS_STRIDE 136
#define AS_FLOATS (128 * AS_STRIDE)
#define BS_FLOATS (32 * BS_STRIDE)
#define SM_FLOATS (2 * AS_FLOATS + 2 * BS_FLOATS)

__device__ __forceinline__ uint32_t smem_u32(const void* p) {
    uint32_t a;
    asm("{ .reg .u64 t; cvta.to.shared.u64 t, %1; cvt.u32.u64 %0, t; }" : "=r"(a) : "l"(p));
    return a;
}
#define CP_ASYNC16(smaddr, gptr) \
    asm volatile("cp.async.ca.shared.global [%0], [%1], 16;" :: "r"(smaddr), "l"(gptr))
#define CP_COMMIT() asm volatile("cp.async.commit_group;" ::: "memory")
#define CP_WAIT1()  asm volatile("cp.async.wait_group 1;" ::: "memory")
#define CP_WAIT0()  asm volatile("cp.async.wait_group 0;" ::: "memory")

__device__ __forceinline__ void mma_tf32(float* c, const uint32_t* a, uint32_t b0, uint32_t b1) {
    asm volatile(
        "mma.sync.aligned.m16n8k8.row.col.f32.tf32.tf32.f32 "
        "{%0,%1,%2,%3}, {%4,%5,%6,%7}, {%8,%9}, {%0,%1,%2,%3};"
        : "+f"(c[0]), "+f"(c[1]), "+f"(c[2]), "+f"(c[3])
        : "r"(a[0]), "r"(a[1]), "r"(a[2]), "r"(a[3]), "r"(b0), "r"(b1));
}

__global__ __launch_bounds__(512, 2) void k_gemm_mma(
    const float* __restrict__ nodes,
    const void* __restrict__ usrc, const void* __restrict__ utgt,
    const float* __restrict__ Ws, const float* __restrict__ Wv,
    const float* __restrict__ bs, const float* __restrict__ bv,
    const float* __restrict__ Wa, int Ms, int Mt)
{
    extern __shared__ float sm[];
    const int which = blockIdx.z;
    const void* __restrict__ uidx = which ? utgt : usrc;
    const float* __restrict__ W = which ? Wv : Ws;
    const float* __restrict__ bias = which ? bv : bs;
    const int M = which ? Mt : Ms;

    const int t = threadIdx.x;
    const int tile_m = blockIdx.x * 128;
    const int tile_n = blockIdx.y * 128;
    if (tile_m >= M) return;
    const int is64 = g_idx64;

    // ---- load mappings ----
    // A: 128 rows x 32 floats; thread t -> row t>>2, two float4 at (t&3)*4 and (t&3)*4+16
    const int ar = t >> 2;
    const int aq = (t & 3) * 4;
    const int mclamp = min(tile_m + ar, M - 1);
    const long gath = (long)IDX(uidx, mclamp >> 1, is64) * BATCH + (mclamp & 1);
    const float* __restrict__ aptr = nodes + gath * IN_DIM + aq;
    // B: 32 k-rows x 128 cols; thread t -> row t>>4, two float4 at (t&15)*4 and +64
    const int bk = t >> 4;
    const int bq = (t & 15) * 4;
    const float* __restrict__ bptr = W + (long)bk * OUT_DIM + tile_n + bq;

    const uint32_t sb = smem_u32(sm);
    const uint32_t a_sm0 = sb + (ar * AS_STRIDE + aq) * 4;
    const uint32_t a_sm1 = a_sm0 + 16 * 4;
    const uint32_t b_sm0 = sb + (2 * AS_FLOATS + bk * BS_STRIDE + bq) * 4;
    const uint32_t b_sm1 = b_sm0 + 64 * 4;

    // ---- fragment mapping: 4x4 warp grid, warp tile 32x32 ----
    const int wid = t >> 5, lane = t & 31;
    const int g = lane >> 2, tg = lane & 3;
    const int wm = (wid >> 2) * 32;
    const int wn = (wid & 3) * 32;

    float acc[2][4][4];
#pragma unroll
    for (int i = 0; i < 2; i++)
#pragma unroll
        for (int j = 0; j < 4; j++)
#pragma unroll
            for (int q = 0; q < 4; q++) acc[i][j][q] = 0.f;

    // ---- pipeline ----
    CP_ASYNC16(a_sm0, aptr);
    CP_ASYNC16(a_sm1, aptr + 16);
    CP_ASYNC16(b_sm0, bptr);
    CP_ASYNC16(b_sm1, bptr + 64);
    CP_COMMIT();

    for (int c = 0; c < 8; c++) {
        const int buf = c & 1;
        if (c < 7) {
            const int kb = (c + 1) * 32;
            const uint32_t ab = (buf ^ 1) * (AS_FLOATS * 4);
            const uint32_t bb = (buf ^ 1) * (BS_FLOATS * 4);
            CP_ASYNC16(a_sm0 + ab, aptr + kb);
            CP_ASYNC16(a_sm1 + ab, aptr + kb + 16);
            CP_ASYNC16(b_sm0 + bb, bptr + (long)kb * OUT_DIM);
            CP_ASYNC16(b_sm1 + bb, bptr + (long)kb * OUT_DIM + 64);
            CP_COMMIT();
            CP_WAIT1();
        } else {
            CP_WAIT0();
        }
        __syncthreads();

        const float* __restrict__ A = sm + buf * AS_FLOATS;
        const float* __restrict__ B = sm + 2 * AS_FLOATS + buf * BS_FLOATS;
#pragma unroll
        for (int k0 = 0; k0 < 32; k0 += 8) {
            uint32_t a0[4], a1[4];
            a0[0] = __float_as_uint(A[(wm + g)      * AS_STRIDE + k0 + tg]);
            a0[1] = __float_as_uint(A[(wm + g + 8)  * AS_STRIDE + k0 + tg]);
            a0[2] = __float_as_uint(A[(wm + g)      * AS_STRIDE + k0 + tg + 4]);
            a0[3] = __float_as_uint(A[(wm + g + 8)  * AS_STRIDE + k0 + tg + 4]);
            a1[0] = __float_as_uint(A[(wm + 16 + g)     * AS_STRIDE + k0 + tg]);
            a1[1] = __float_as_uint(A[(wm + 16 + g + 8) * AS_STRIDE + k0 + tg]);
            a1[2] = __float_as_uint(A[(wm + 16 + g)     * AS_STRIDE + k0 + tg + 4]);
            a1[3] = __float_as_uint(A[(wm + 16 + g + 8) * AS_STRIDE + k0 + tg + 4]);
#pragma unroll
            for (int bx = 0; bx < 4; bx++) {
                uint32_t b0 = __float_as_uint(B[(k0 + tg)     * BS_STRIDE + wn + bx * 8 + g]);
                uint32_t b1 = __float_as_uint(B[(k0 + tg + 4) * BS_STRIDE + wn + bx * 8 + g]);
                mma_tf32(acc[0][bx], a0, b0, b1);
                mma_tf32(acc[1][bx], a1, b0, b1);
            }
        }
        __syncthreads();
    }

    // ---- epilogue ----
    const int slot = blockIdx.y * 4 + (wid & 3);
#pragma unroll
    for (int am = 0; am < 2; am++) {
        const int m0 = tile_m + wm + am * 16 + g;
        const int m1 = m0 + 8;
        float d0 = 0.f, d1 = 0.f;
#pragma unroll
        for (int bx = 0; bx < 4; bx++) {
            const int col = tile_n + wn + bx * 8 + tg * 2;
            const float bi0 = bias[col], bi1 = bias[col + 1];
            float v00 = acc[am][bx][0] + bi0, v01 = acc[am][bx][1] + bi1;
            float v10 = acc[am][bx][2] + bi0, v11 = acc[am][bx][3] + bi1;
            if (which == 0) {
                const float wa0 = Wa[col], wa1 = Wa[col + 1];
                d0 = fmaf(v00, wa0, fmaf(v01, wa1, d0));
                d1 = fmaf(v10, wa0, fmaf(v11, wa1, d1));
                if (m0 < M)
                    *reinterpret_cast<float2*>(g_src_proj + (long)m0 * OUT_DIM + col) =
                        make_float2(v00, v01);
                if (m1 < M)
                    *reinterpret_cast<float2*>(g_src_proj + (long)m1 * OUT_DIM + col) =
                        make_float2(v10, v11);
            } else {
                if (m0 < M)
                    *reinterpret_cast<__half2*>(g_vals_h + (long)m0 * OUT_DIM + col) =
                        __floats2half2_rn(v00, v01);
                if (m1 < M)
                    *reinterpret_cast<__half2*>(g_vals_h + (long)m1 * OUT_DIM + col) =
                        __floats2half2_rn(v10, v11);
            }
        }
        if (which == 0) {
            d0 += __shfl_xor_sync(0xFFFFFFFFu, d0, 1);
            d0 += __shfl_xor_sync(0xFFFFFFFFu, d0, 2);
            d1 += __shfl_xor_sync(0xFFFFFFFFu, d1, 1);
            d1 += __shfl_xor_sync(0xFFFFFFFFu, d1, 2);
            if (tg == 0) {
                if (m0 < M) g_sdot_part[slot][m0] = d0;
                if (m1 < M) g_sdot_part[slot][m1] = d1;
            }
        }
    }
}

// ---------------- edge: ex + segment bounds (sorted sid) --------------------
__global__ void k_edge(const void* __restrict__ sidp, const void* __restrict__ tidp,
                       const float* __restrict__ ba, int E) {
    int e = blockIdx.x * blockDim.x + threadIdx.x;
    if (e >= E) return;
    const int is64 = g_idx64;
    const int s = IDX(sidp, e, is64);
    if (e == 0 || IDX(sidp, e - 1, is64) != s) g_seg_start[s] = e;
    if (e == E - 1 || IDX(sidp, e + 1, is64) != s) g_seg_end[s] = e + 1;
    const int tg = IDX(tidp, e, is64);
    const float b0 = ba[0];
#pragma unroll
    for (int b = 0; b < BATCH; b++) {
        float sd = ((g_sdot_part[0][s * 2 + b] + g_sdot_part[1][s * 2 + b])
                  + (g_sdot_part[2][s * 2 + b] + g_sdot_part[3][s * 2 + b]))
                 + ((g_sdot_part[4][s * 2 + b] + g_sdot_part[5][s * 2 + b])
                  + (g_sdot_part[6][s * 2 + b] + g_sdot_part[7][s * 2 + b]));
        float sc = sd + g_tdot[tg * 2 + b] + b0;
        sc = (sc >= 0.f) ? sc : SLOPE * sc;
        sc = fminf(2.f, fmaxf(-2.f, sc));
        g_ex[e * 2 + b] = expf(sc);
    }
}

// deterministic segment-sum of ex
__global__ void k_denom(int Ns) {
    int i = blockIdx.x * blockDim.x + threadIdx.x;
    if (i >= Ns * BATCH) return;
    int n = i >> 1, b = i & 1;
    int s0 = g_seg_start[n], s1 = g_seg_end[n];
    float d = 0.f;
    for (int e = s0; e < s1; e++) d += g_ex[e * 2 + b];
    g_denom[i] = d;
}

// pack per-edge: w = alpha[tid[e]], row = tid[tid[e]]
__global__ void k_pack(const void* __restrict__ sidp, const void* __restrict__ tidp,
                       int E) {
    int e = blockIdx.x * blockDim.x + threadIdx.x;
    if (e >= E) return;
    const int is64 = g_idx64;
    const int j = IDX(tidp, e, is64);       // edge index (faithful bug)
    const int sj = IDX(sidp, j, is64);
    float w0 = g_ex[j * 2 + 0] / g_denom[sj * 2 + 0];
    float w1 = g_ex[j * 2 + 1] / g_denom[sj * 2 + 1];
    g_w[e] = make_float2(w0, w1);
    g_row[e] = IDX(tidp, j, is64);
}

// ---------------- aggregation (packed stream, unrolled MLP) -----------------
__global__ __launch_bounds__(512) void k_agg(float* __restrict__ out, int Ns) {
    __shared__ float2 ws[32];
    __shared__ int rs[32];
    const int n = blockIdx.x;
    const int t = threadIdx.x;
    const int b = t >> 8;
    const int o = t & 255;
    const int s0 = g_seg_start[n], s1 = g_seg_end[n];
    const int cnt = s1 - s0;
    const long outrow = ((long)n * BATCH + b) * OUT_DIM + o;
    float a0 = g_src_proj[outrow], a1 = 0.f, a2 = 0.f, a3 = 0.f;

    if (cnt == 16) {
        if (t < 16) { ws[t] = g_w[s0 + t]; rs[t] = g_row[s0 + t]; }
        __syncthreads();
        float w[16], v[16];
#pragma unroll
        for (int i = 0; i < 16; i++) {
            w[i] = b ? ws[i].y : ws[i].x;
            v[i] = __half2float(g_vals_h[(((long)rs[i] << 1) + b) * OUT_DIM + o]);
        }
#pragma unroll
        for (int i = 0; i < 16; i += 4) {
            a0 = fmaf(w[i],     v[i],     a0);
            a1 = fmaf(w[i + 1], v[i + 1], a1);
            a2 = fmaf(w[i + 2], v[i + 2], a2);
            a3 = fmaf(w[i + 3], v[i + 3], a3);
        }
    } else {
        for (int base = s0; base < s1; base += 32) {
            int c = min(32, s1 - base);
            if (t < c) { ws[t] = g_w[base + t]; rs[t] = g_row[base + t]; }
            __syncthreads();
            for (int i = 0; i < c; i++) {
                float w = b ? ws[i].y : ws[i].x;
                float v = __half2float(g_vals_h[(((long)rs[i] << 1) + b) * OUT_DIM + o]);
                a0 = fmaf(w, v, a0);
            }
            __syncthreads();
        }
    }
    out[outrow] = (a0 + a1) + (a2 + a3);
}

extern "C" void kernel_launch(void* const* d_in, const int* in_sizes, int n_in,
                              void* d_out, int out_size) {
    const float* nodes = (const float*)d_in[0];
    const float* Ws    = (const float*)d_in[1];
    const float* bs    = (const float*)d_in[2];
    const float* Wt    = (const float*)d_in[3];
    const float* bt    = (const float*)d_in[4];
    const float* Wv    = (const float*)d_in[5];
    const float* bv    = (const float*)d_in[6];
    const float* Wa    = (const float*)d_in[7];
    const float* ba    = (const float*)d_in[8];
    const void* usrc   = d_in[9];
    const void* utgt   = d_in[10];
    const void* sidp   = d_in[11];
    const void* tidp   = d_in[12];

    const int Ns = in_sizes[9];
    const int Nt = in_sizes[10];
    const int E  = in_sizes[11];
    float* out = (float*)d_out;

    static int smem_set = 0;
    if (!smem_set) {
        cudaFuncSetAttribute(k_gemm_mma, cudaFuncAttributeMaxDynamicSharedMemorySize,
                             SM_FLOATS * 4);
        smem_set = 1;
    }

    const int Ms = Ns * BATCH;
    const int Mt = Nt * BATCH;

    k_prep<<<33, 256>>>(usrc, Wt, bt, Wa);
    k_tdot<<<(Mt * 32 + 255) / 256, 256>>>(nodes, utgt, Mt);

    const int Mmax = (Ms > Mt) ? Ms : Mt;
    dim3 gg((Mmax + 127) / 128, OUT_DIM / 128, 2);
    k_gemm_mma<<<gg, 512, SM_FLOATS * 4>>>(nodes, usrc, utgt, Ws, Wv, bs, bv, Wa, Ms, Mt);

    k_edge<<<(E + 255) / 256, 256>>>(sidp, tidp, ba, E);
    k_denom<<<(Ns * BATCH + 255) / 256, 256>>>(Ns);
    k_pack<<<(E + 255) / 256, 256>>>(sidp, tidp, E);

    k_agg<<<Ns, 512>>>(out, Ns);
}

// round 10
// speedup vs baseline: 1.3043x; 1.1422x over previous
#include <cuda_runtime.h>
#include <cuda_fp16.h>
#include <math.h>
#include <stdint.h>

#define IN_DIM 256
#define OUT_DIM 256
#define BATCH 2
#define MAXN 10240
#define MAXE 163840
#define SLOPE 0.2f

// ---------------- scratch (static device globals; no allocation) ----------
static __device__ float  g_src_proj[MAXN * BATCH * OUT_DIM];    // 20 MB
static __device__ __half g_vals_h[MAXN * BATCH * OUT_DIM];      // 10 MB
static __device__ __half g_nodes_h[MAXN * BATCH * IN_DIM];      // 10 MB
static __device__ __half g_WhT[2 * IN_DIM * OUT_DIM];           // W^T fp16
static __device__ float  g_sdot_part[8][MAXN * BATCH];
static __device__ float  g_tdot[MAXN * BATCH];
static __device__ float  g_denom[MAXN * BATCH];
static __device__ float  g_ex[MAXE * BATCH];
static __device__ float2 g_w[MAXE];
static __device__ int    g_row[MAXE];
static __device__ int    g_seg_start[MAXN];
static __device__ int    g_seg_end[MAXN];
static __device__ float  g_wta[IN_DIM];
static __device__ float  g_ct;
static __device__ int    g_idx64;

// ---------------- index dtype handling -------------------------------------
__device__ __forceinline__ int IDX(const void* p, int i, int is64) {
    if (is64) return (int)(((const long long*)p)[i]);
    return ((const int*)p)[i];
}

// ---------------- fused prep: detect + ct + wta + fp16 conversions ----------
// block 0              : detect + ct
// blocks [1, 33)       : wta (warp per k)
// blocks [33, 33+NC)   : nodes fp32 -> fp16 (2048 elems per block)
// blocks [33+NC, +128) : W transpose+convert: WT[n][k] = W[k][n] (fp16)
__global__ void k_prep(const void* __restrict__ usrc,
                       const float* __restrict__ Wt, const float* __restrict__ bt,
                       const float* __restrict__ Wa,
                       const float* __restrict__ nodes,
                       const float* __restrict__ Ws, const float* __restrict__ Wv,
                       int ntot, int NC) {
    const int bid = blockIdx.x;
    const int t = threadIdx.x;
    if (bid == 0) {
        if (t == 0) {
            const int* p = (const int*)usrc;
            g_idx64 = (p[1] == 0 && p[3] == 0) ? 1 : 0;
        }
        __shared__ float red[256];
        red[t] = bt[t] * Wa[OUT_DIM + t];
        __syncthreads();
        for (int st = 128; st > 0; st >>= 1) {
            if (t < st) red[t] += red[t + st];
            __syncthreads();
        }
        if (t == 0) g_ct = red[0];
    } else if (bid < 33) {
        const int k = (bid - 1) * 8 + (t >> 5);
        const int lane = t & 31;
        const float* wrow = Wt + (long)k * OUT_DIM;
        float s = 0.f;
#pragma unroll
        for (int o = lane; o < OUT_DIM; o += 32) s = fmaf(wrow[o], Wa[OUT_DIM + o], s);
#pragma unroll
        for (int st = 16; st; st >>= 1) s += __shfl_xor_sync(0xFFFFFFFFu, s, st);
        if (lane == 0) g_wta[k] = s;
    } else if (bid < 33 + NC) {
        long idx = (long)(bid - 33) * 2048 + t * 8;
        if (idx + 8 <= ntot) {
            float4 v0 = *reinterpret_cast<const float4*>(nodes + idx);
            float4 v1 = *reinterpret_cast<const float4*>(nodes + idx + 4);
            __half2 h0 = __floats2half2_rn(v0.x, v0.y);
            __half2 h1 = __floats2half2_rn(v0.z, v0.w);
            __half2 h2 = __floats2half2_rn(v1.x, v1.y);
            __half2 h3 = __floats2half2_rn(v1.z, v1.w);
            uint4 o;
            o.x = *reinterpret_cast<uint32_t*>(&h0);
            o.y = *reinterpret_cast<uint32_t*>(&h1);
            o.z = *reinterpret_cast<uint32_t*>(&h2);
            o.w = *reinterpret_cast<uint32_t*>(&h3);
            *reinterpret_cast<uint4*>(g_nodes_h + idx) = o;
        }
    } else {
        const int j = bid - 33 - NC;          // 0..127
        const int which = j >> 6;
        const float* __restrict__ W = which ? Wv : Ws;
        const int n = (j & 63) * 4 + (t >> 6);    // n row
        const int k = (t & 63) * 4;
        __half* dst = g_WhT + (long)which * IN_DIM * OUT_DIM + (long)n * IN_DIM + k;
#pragma unroll
        for (int q = 0; q < 4; q++)
            dst[q] = __float2half_rn(W[(long)(k + q) * OUT_DIM + n]);
    }
}

// ---------------- tdot (warp per row, fp32 nodes) ---------------------------
__global__ void k_tdot(const float* __restrict__ nodes, const void* __restrict__ utgt,
                       int Mt) {
    int m = (blockIdx.x * blockDim.x + threadIdx.x) >> 5;
    int lane = threadIdx.x & 31;
    if (m >= Mt) return;
    int is64 = g_idx64;
    int nidx = m >> 1, b = m & 1;
    long gidx = (long)IDX(utgt, nidx, is64) * BATCH + b;
    const float* row = nodes + gidx * IN_DIM;
    float s = 0.f;
#pragma unroll
    for (int o = lane; o < IN_DIM; o += 32) s = fmaf(row[o], g_wta[o], s);
#pragma unroll
    for (int st = 16; st; st >>= 1) s += __shfl_xor_sync(0xFFFFFFFFu, s, st);
    if (lane == 0) g_tdot[m] = s + g_ct;
}

// ---------------- fp16 mma.sync gathered GEMM (512 threads, 16 warps) -------
// z=0: g_src_proj = nodes_h[usrc] @ Ws + bs (fp32) + sdot partials fused
// z=1: g_vals_h   = nodes_h[utgt] @ Wv + bv (fp16)
// CTA tile 128x128, K chunk 32 halves, warp tile 32x32, m16n8k16.f16.
#define AH_STRIDE 40                      // halves per A/B smem row (pad 8)
#define AH_HALVES (128 * AH_STRIDE)       // 5120
#define SMH_TOTAL (4 * AH_HALVES)         // A0,A1,B0,B1 = 20480 halves = 40960 B

__device__ __forceinline__ uint32_t smem_u32(const void* p) {
    uint32_t a;
    asm("{ .reg .u64 t; cvta.to.shared.u64 t, %1; cvt.u32.u64 %0, t; }" : "=r"(a) : "l"(p));
    return a;
}
#define CP_ASYNC16(smaddr, gptr) \
    asm volatile("cp.async.ca.shared.global [%0], [%1], 16;" :: "r"(smaddr), "l"(gptr))
#define CP_COMMIT() asm volatile("cp.async.commit_group;" ::: "memory")
#define CP_WAIT1()  asm volatile("cp.async.wait_group 1;" ::: "memory")
#define CP_WAIT0()  asm volatile("cp.async.wait_group 0;" ::: "memory")

__device__ __forceinline__ void mma_f16(float* c, const uint32_t* a, uint32_t b0, uint32_t b1) {
    asm volatile(
        "mma.sync.aligned.m16n8k16.row.col.f32.f16.f16.f32 "
        "{%0,%1,%2,%3}, {%4,%5,%6,%7}, {%8,%9}, {%0,%1,%2,%3};"
        : "+f"(c[0]), "+f"(c[1]), "+f"(c[2]), "+f"(c[3])
        : "r"(a[0]), "r"(a[1]), "r"(a[2]), "r"(a[3]), "r"(b0), "r"(b1));
}

__global__ __launch_bounds__(512, 2) void k_gemm_mma(
    const void* __restrict__ usrc, const void* __restrict__ utgt,
    const float* __restrict__ bs, const float* __restrict__ bv,
    const float* __restrict__ Wa, int Ms, int Mt)
{
    extern __shared__ __half smh[];
    const int which = blockIdx.z;
    const void* __restrict__ uidx = which ? utgt : usrc;
    const float* __restrict__ bias = which ? bv : bs;
    const int M = which ? Mt : Ms;

    const int t = threadIdx.x;
    const int tile_m = blockIdx.x * 128;
    const int tile_n = blockIdx.y * 128;
    if (tile_m >= M) return;
    const int is64 = g_idx64;

    // ---- load mappings (one 16B cp.async each for A and B per chunk) ----
    const int ar = t >> 2;                 // A row 0..127
    const int ak = (t & 3) * 8;            // A k-offset (halves)
    const int mclamp = min(tile_m + ar, M - 1);
    const long gath = (long)IDX(uidx, mclamp >> 1, is64) * BATCH + (mclamp & 1);
    const __half* __restrict__ aptr = g_nodes_h + gath * IN_DIM + ak;
    // B (transposed W): row = n, cols = k
    const __half* __restrict__ bptr =
        g_WhT + (long)which * IN_DIM * OUT_DIM + (long)(tile_n + ar) * IN_DIM + ak;

    const uint32_t sb = smem_u32(smh);
    const uint32_t a_sm = sb + (ar * AH_STRIDE + ak) * 2;
    const uint32_t b_sm = a_sm + 2 * AH_HALVES * 2;

    // ---- fragment mapping: 4x4 warp grid, warp tile 32x32 ----
    const int wid = t >> 5, lane = t & 31;
    const int g = lane >> 2, tg = lane & 3;
    const int wm = (wid >> 2) * 32;
    const int wn = (wid & 3) * 32;

    float acc[2][4][4];
#pragma unroll
    for (int i = 0; i < 2; i++)
#pragma unroll
        for (int j = 0; j < 4; j++)
#pragma unroll
            for (int q = 0; q < 4; q++) acc[i][j][q] = 0.f;

    // ---- pipeline ----
    CP_ASYNC16(a_sm, aptr);
    CP_ASYNC16(b_sm, bptr);
    CP_COMMIT();

    for (int c = 0; c < 8; c++) {
        const int buf = c & 1;
        if (c < 7) {
            const int kb = (c + 1) * 32;
            const uint32_t off = (buf ^ 1) * (AH_HALVES * 2);
            CP_ASYNC16(a_sm + off, aptr + kb);
            CP_ASYNC16(b_sm + off, bptr + kb);
            CP_COMMIT();
            CP_WAIT1();
        } else {
            CP_WAIT0();
        }
        __syncthreads();

        const __half* __restrict__ A = smh + buf * AH_HALVES;
        const __half* __restrict__ B = smh + (2 + buf) * AH_HALVES;
#pragma unroll
        for (int k0 = 0; k0 < 32; k0 += 16) {
            uint32_t a0[4], a1[4];
            const int kc = k0 + 2 * tg;
            a0[0] = *reinterpret_cast<const uint32_t*>(A + (wm + g)      * AH_STRIDE + kc);
            a0[1] = *reinterpret_cast<const uint32_t*>(A + (wm + g + 8)  * AH_STRIDE + kc);
            a0[2] = *reinterpret_cast<const uint32_t*>(A + (wm + g)      * AH_STRIDE + kc + 8);
            a0[3] = *reinterpret_cast<const uint32_t*>(A + (wm + g + 8)  * AH_STRIDE + kc + 8);
            a1[0] = *reinterpret_cast<const uint32_t*>(A + (wm + 16 + g)     * AH_STRIDE + kc);
            a1[1] = *reinterpret_cast<const uint32_t*>(A + (wm + 16 + g + 8) * AH_STRIDE + kc);
            a1[2] = *reinterpret_cast<const uint32_t*>(A + (wm + 16 + g)     * AH_STRIDE + kc + 8);
            a1[3] = *reinterpret_cast<const uint32_t*>(A + (wm + 16 + g + 8) * AH_STRIDE + kc + 8);
#pragma unroll
            for (int bx = 0; bx < 4; bx++) {
                const int nrow = wn + bx * 8 + g;
                uint32_t b0 = *reinterpret_cast<const uint32_t*>(B + nrow * AH_STRIDE + kc);
                uint32_t b1 = *reinterpret_cast<const uint32_t*>(B + nrow * AH_STRIDE + kc + 8);
                mma_f16(acc[0][bx], a0, b0, b1);
                mma_f16(acc[1][bx], a1, b0, b1);
            }
        }
        __syncthreads();
    }

    // ---- epilogue ----
    const int slot = blockIdx.y * 4 + (wid & 3);
#pragma unroll
    for (int am = 0; am < 2; am++) {
        const int m0 = tile_m + wm + am * 16 + g;
        const int m1 = m0 + 8;
        float d0 = 0.f, d1 = 0.f;
#pragma unroll
        for (int bx = 0; bx < 4; bx++) {
            const int col = tile_n + wn + bx * 8 + tg * 2;
            const float bi0 = bias[col], bi1 = bias[col + 1];
            float v00 = acc[am][bx][0] + bi0, v01 = acc[am][bx][1] + bi1;
            float v10 = acc[am][bx][2] + bi0, v11 = acc[am][bx][3] + bi1;
            if (which == 0) {
                const float wa0 = Wa[col], wa1 = Wa[col + 1];
                d0 = fmaf(v00, wa0, fmaf(v01, wa1, d0));
                d1 = fmaf(v10, wa0, fmaf(v11, wa1, d1));
                if (m0 < M)
                    *reinterpret_cast<float2*>(g_src_proj + (long)m0 * OUT_DIM + col) =
                        make_float2(v00, v01);
                if (m1 < M)
                    *reinterpret_cast<float2*>(g_src_proj + (long)m1 * OUT_DIM + col) =
                        make_float2(v10, v11);
            } else {
                if (m0 < M)
                    *reinterpret_cast<__half2*>(g_vals_h + (long)m0 * OUT_DIM + col) =
                        __floats2half2_rn(v00, v01);
                if (m1 < M)
                    *reinterpret_cast<__half2*>(g_vals_h + (long)m1 * OUT_DIM + col) =
                        __floats2half2_rn(v10, v11);
            }
        }
        if (which == 0) {
            d0 += __shfl_xor_sync(0xFFFFFFFFu, d0, 1);
            d0 += __shfl_xor_sync(0xFFFFFFFFu, d0, 2);
            d1 += __shfl_xor_sync(0xFFFFFFFFu, d1, 1);
            d1 += __shfl_xor_sync(0xFFFFFFFFu, d1, 2);
            if (tg == 0) {
                if (m0 < M) g_sdot_part[slot][m0] = d0;
                if (m1 < M) g_sdot_part[slot][m1] = d1;
            }
        }
    }
}

// ---------------- edge: ex + segment bounds (sorted sid) --------------------
__global__ void k_edge(const void* __restrict__ sidp, const void* __restrict__ tidp,
                       const float* __restrict__ ba, int E) {
    int e = blockIdx.x * blockDim.x + threadIdx.x;
    if (e >= E) return;
    const int is64 = g_idx64;
    const int s = IDX(sidp, e, is64);
    if (e == 0 || IDX(sidp, e - 1, is64) != s) g_seg_start[s] = e;
    if (e == E - 1 || IDX(sidp, e + 1, is64) != s) g_seg_end[s] = e + 1;
    const int tg = IDX(tidp, e, is64);
    const float b0 = ba[0];
#pragma unroll
    for (int b = 0; b < BATCH; b++) {
        float sd = ((g_sdot_part[0][s * 2 + b] + g_sdot_part[1][s * 2 + b])
                  + (g_sdot_part[2][s * 2 + b] + g_sdot_part[3][s * 2 + b]))
                 + ((g_sdot_part[4][s * 2 + b] + g_sdot_part[5][s * 2 + b])
                  + (g_sdot_part[6][s * 2 + b] + g_sdot_part[7][s * 2 + b]));
        float sc = sd + g_tdot[tg * 2 + b] + b0;
        sc = (sc >= 0.f) ? sc : SLOPE * sc;
        sc = fminf(2.f, fmaxf(-2.f, sc));
        g_ex[e * 2 + b] = expf(sc);
    }
}

// deterministic segment-sum of ex
__global__ void k_denom(int Ns) {
    int i = blockIdx.x * blockDim.x + threadIdx.x;
    if (i >= Ns * BATCH) return;
    int n = i >> 1, b = i & 1;
    int s0 = g_seg_start[n], s1 = g_seg_end[n];
    float d = 0.f;
    for (int e = s0; e < s1; e++) d += g_ex[e * 2 + b];
    g_denom[i] = d;
}

// pack per-edge: w = alpha[tid[e]], row = tid[tid[e]]
__global__ void k_pack(const void* __restrict__ sidp, const void* __restrict__ tidp,
                       int E) {
    int e = blockIdx.x * blockDim.x + threadIdx.x;
    if (e >= E) return;
    const int is64 = g_idx64;
    const int j = IDX(tidp, e, is64);       // edge index (faithful bug)
    const int sj = IDX(sidp, j, is64);
    float w0 = g_ex[j * 2 + 0] / g_denom[sj * 2 + 0];
    float w1 = g_ex[j * 2 + 1] / g_denom[sj * 2 + 1];
    g_w[e] = make_float2(w0, w1);
    g_row[e] = IDX(tidp, j, is64);
}

// ---------------- aggregation (packed stream, unrolled MLP) -----------------
__global__ __launch_bounds__(512) void k_agg(float* __restrict__ out, int Ns) {
    __shared__ float2 ws[32];
    __shared__ int rs[32];
    const int n = blockIdx.x;
    const int t = threadIdx.x;
    const int b = t >> 8;
    const int o = t & 255;
    const int s0 = g_seg_start[n], s1 = g_seg_end[n];
    const int cnt = s1 - s0;
    const long outrow = ((long)n * BATCH + b) * OUT_DIM + o;
    float a0 = g_src_proj[outrow], a1 = 0.f, a2 = 0.f, a3 = 0.f;

    if (cnt == 16) {
        if (t < 16) { ws[t] = g_w[s0 + t]; rs[t] = g_row[s0 + t]; }
        __syncthreads();
        float w[16], v[16];
#pragma unroll
        for (int i = 0; i < 16; i++) {
            w[i] = b ? ws[i].y : ws[i].x;
            v[i] = __half2float(g_vals_h[(((long)rs[i] << 1) + b) * OUT_DIM + o]);
        }
#pragma unroll
        for (int i = 0; i < 16; i += 4) {
            a0 = fmaf(w[i],     v[i],     a0);
            a1 = fmaf(w[i + 1], v[i + 1], a1);
            a2 = fmaf(w[i + 2], v[i + 2], a2);
            a3 = fmaf(w[i + 3], v[i + 3], a3);
        }
    } else {
        for (int base = s0; base < s1; base += 32) {
            int c = min(32, s1 - base);
            if (t < c) { ws[t] = g_w[base + t]; rs[t] = g_row[base + t]; }
            __syncthreads();
            for (int i = 0; i < c; i++) {
                float w = b ? ws[i].y : ws[i].x;
                float v = __half2float(g_vals_h[(((long)rs[i] << 1) + b) * OUT_DIM + o]);
                a0 = fmaf(w, v, a0);
            }
            __syncthreads();
        }
    }
    out[outrow] = (a0 + a1) + (a2 + a3);
}

extern "C" void kernel_launch(void* const* d_in, const int* in_sizes, int n_in,
                              void* d_out, int out_size) {
    const float* nodes = (const float*)d_in[0];
    const float* Ws    = (const float*)d_in[1];
    const float* bs    = (const float*)d_in[2];
    const float* Wt    = (const float*)d_in[3];
    const float* bt    = (const float*)d_in[4];
    const float* Wv    = (const float*)d_in[5];
    const float* bv    = (const float*)d_in[6];
    const float* Wa    = (const float*)d_in[7];
    const float* ba    = (const float*)d_in[8];
    const void* usrc   = d_in[9];
    const void* utgt   = d_in[10];
    const void* sidp   = d_in[11];
    const void* tidp   = d_in[12];

    const int Ns = in_sizes[9];
    const int Nt = in_sizes[10];
    const int E  = in_sizes[11];
    const int ntot = in_sizes[0];
    float* out = (float*)d_out;

    static int smem_set = 0;
    if (!smem_set) {
        cudaFuncSetAttribute(k_gemm_mma, cudaFuncAttributeMaxDynamicSharedMemorySize,
                             SMH_TOTAL * 2);
        smem_set = 1;
    }

    const int Ms = Ns * BATCH;
    const int Mt = Nt * BATCH;
    const int NC = (ntot + 2047) / 2048;

    k_prep<<<33 + NC + 128, 256>>>(usrc, Wt, bt, Wa, nodes, Ws, Wv, ntot, NC);
    k_tdot<<<(Mt * 32 + 255) / 256, 256>>>(nodes, utgt, Mt);

    const int Mmax = (Ms > Mt) ? Ms : Mt;
    dim3 gg((Mmax + 127) / 128, OUT_DIM / 128, 2);
    k_gemm_mma<<<gg, 512, SMH_TOTAL * 2>>>(usrc, utgt, bs, bv, Wa, Ms, Mt);

    k_edge<<<(E + 255) / 256, 256>>>(sidp, tidp, ba, E);
    k_denom<<<(Ns * BATCH + 255) / 256, 256>>>(Ns);
    k_pack<<<(E + 255) / 256, 256>>>(sidp, tidp, E);

    k_agg<<<Ns, 512>>>(out, Ns);
}

// round 11
// speedup vs baseline: 1.4550x; 1.1155x over previous
#include <cuda_runtime.h>
#include <cuda_fp16.h>
#include <math.h>
#include <stdint.h>

#define IN_DIM 256
#define OUT_DIM 256
#define BATCH 2
#define MAXN 10240
#define MAXE 163840
#define SLOPE 0.2f

// ---------------- scratch (static device globals; no allocation) ----------
static __device__ float  g_src_proj[MAXN * BATCH * OUT_DIM];    // 20 MB
static __device__ __half g_vals_h[MAXN * BATCH * OUT_DIM];      // 10 MB
static __device__ __half g_nodes_h[MAXN * BATCH * IN_DIM];      // 10 MB
static __device__ __half g_WhT[2 * IN_DIM * OUT_DIM];           // W^T fp16
static __device__ float  g_sdot_part[8][MAXN * BATCH];
static __device__ float  g_tdot[MAXN * BATCH];
static __device__ float  g_denom[MAXN * BATCH];
static __device__ float  g_ex[MAXE * BATCH];
static __device__ int    g_seg_start[MAXN];
static __device__ int    g_seg_end[MAXN];
static __device__ float  g_wta[IN_DIM];
static __device__ float  g_ct;
static __device__ int    g_idx64;

// ---------------- index dtype handling -------------------------------------
__device__ __forceinline__ int IDX(const void* p, int i, int is64) {
    if (is64) return (int)(((const long long*)p)[i]);
    return ((const int*)p)[i];
}

// ---------------- fused prep: detect + ct + wta + fp16 conversions ----------
__global__ void k_prep(const void* __restrict__ usrc,
                       const float* __restrict__ Wt, const float* __restrict__ bt,
                       const float* __restrict__ Wa,
                       const float* __restrict__ nodes,
                       const float* __restrict__ Ws, const float* __restrict__ Wv,
                       int ntot, int NC) {
    const int bid = blockIdx.x;
    const int t = threadIdx.x;
    if (bid == 0) {
        if (t == 0) {
            const int* p = (const int*)usrc;
            g_idx64 = (p[1] == 0 && p[3] == 0) ? 1 : 0;
        }
        __shared__ float red[256];
        red[t] = bt[t] * Wa[OUT_DIM + t];
        __syncthreads();
        for (int st = 128; st > 0; st >>= 1) {
            if (t < st) red[t] += red[t + st];
            __syncthreads();
        }
        if (t == 0) g_ct = red[0];
    } else if (bid < 33) {
        const int k = (bid - 1) * 8 + (t >> 5);
        const int lane = t & 31;
        const float* wrow = Wt + (long)k * OUT_DIM;
        float s = 0.f;
#pragma unroll
        for (int o = lane; o < OUT_DIM; o += 32) s = fmaf(wrow[o], Wa[OUT_DIM + o], s);
#pragma unroll
        for (int st = 16; st; st >>= 1) s += __shfl_xor_sync(0xFFFFFFFFu, s, st);
        if (lane == 0) g_wta[k] = s;
    } else if (bid < 33 + NC) {
        long idx = (long)(bid - 33) * 2048 + t * 8;
        if (idx + 8 <= ntot) {
            float4 v0 = *reinterpret_cast<const float4*>(nodes + idx);
            float4 v1 = *reinterpret_cast<const float4*>(nodes + idx + 4);
            __half2 h0 = __floats2half2_rn(v0.x, v0.y);
            __half2 h1 = __floats2half2_rn(v0.z, v0.w);
            __half2 h2 = __floats2half2_rn(v1.x, v1.y);
            __half2 h3 = __floats2half2_rn(v1.z, v1.w);
            uint4 o;
            o.x = *reinterpret_cast<uint32_t*>(&h0);
            o.y = *reinterpret_cast<uint32_t*>(&h1);
            o.z = *reinterpret_cast<uint32_t*>(&h2);
            o.w = *reinterpret_cast<uint32_t*>(&h3);
            *reinterpret_cast<uint4*>(g_nodes_h + idx) = o;
        }
    } else {
        const int j = bid - 33 - NC;          // 0..127
        const int which = j >> 6;
        const float* __restrict__ W = which ? Wv : Ws;
        const int n = (j & 63) * 4 + (t >> 6);
        const int k = (t & 63) * 4;
        __half* dst = g_WhT + (long)which * IN_DIM * OUT_DIM + (long)n * IN_DIM + k;
#pragma unroll
        for (int q = 0; q < 4; q++)
            dst[q] = __float2half_rn(W[(long)(k + q) * OUT_DIM + n]);
    }
}

// ---------------- tdot (warp per row, fp32 nodes) ---------------------------
__global__ void k_tdot(const float* __restrict__ nodes, const void* __restrict__ utgt,
                       int Mt) {
    int m = (blockIdx.x * blockDim.x + threadIdx.x) >> 5;
    int lane = threadIdx.x & 31;
    if (m >= Mt) return;
    int is64 = g_idx64;
    int nidx = m >> 1, b = m & 1;
    long gidx = (long)IDX(utgt, nidx, is64) * BATCH + b;
    const float* row = nodes + gidx * IN_DIM;
    float s = 0.f;
#pragma unroll
    for (int o = lane; o < IN_DIM; o += 32) s = fmaf(row[o], g_wta[o], s);
#pragma unroll
    for (int st = 16; st; st >>= 1) s += __shfl_xor_sync(0xFFFFFFFFu, s, st);
    if (lane == 0) g_tdot[m] = s + g_ct;
}

// ---------------- fp16 mma.sync gathered GEMM (512 threads, 16 warps) -------
#define AH_STRIDE 40
#define AH_HALVES (128 * AH_STRIDE)
#define SMH_TOTAL (4 * AH_HALVES)

__device__ __forceinline__ uint32_t smem_u32(const void* p) {
    uint32_t a;
    asm("{ .reg .u64 t; cvta.to.shared.u64 t, %1; cvt.u32.u64 %0, t; }" : "=r"(a) : "l"(p));
    return a;
}
#define CP_ASYNC16(smaddr, gptr) \
    asm volatile("cp.async.ca.shared.global [%0], [%1], 16;" :: "r"(smaddr), "l"(gptr))
#define CP_COMMIT() asm volatile("cp.async.commit_group;" ::: "memory")
#define CP_WAIT1()  asm volatile("cp.async.wait_group 1;" ::: "memory")
#define CP_WAIT0()  asm volatile("cp.async.wait_group 0;" ::: "memory")

__device__ __forceinline__ void mma_f16(float* c, const uint32_t* a, uint32_t b0, uint32_t b1) {
    asm volatile(
        "mma.sync.aligned.m16n8k16.row.col.f32.f16.f16.f32 "
        "{%0,%1,%2,%3}, {%4,%5,%6,%7}, {%8,%9}, {%0,%1,%2,%3};"
        : "+f"(c[0]), "+f"(c[1]), "+f"(c[2]), "+f"(c[3])
        : "r"(a[0]), "r"(a[1]), "r"(a[2]), "r"(a[3]), "r"(b0), "r"(b1));
}

__global__ __launch_bounds__(512, 2) void k_gemm_mma(
    const void* __restrict__ usrc, const void* __restrict__ utgt,
    const float* __restrict__ bs, const float* __restrict__ bv,
    const float* __restrict__ Wa, int Ms, int Mt)
{
    extern __shared__ __half smh[];
    const int which = blockIdx.z;
    const void* __restrict__ uidx = which ? utgt : usrc;
    const float* __restrict__ bias = which ? bv : bs;
    const int M = which ? Mt : Ms;

    const int t = threadIdx.x;
    const int tile_m = blockIdx.x * 128;
    const int tile_n = blockIdx.y * 128;
    if (tile_m >= M) return;
    const int is64 = g_idx64;

    const int ar = t >> 2;
    const int ak = (t & 3) * 8;
    const int mclamp = min(tile_m + ar, M - 1);
    const long gath = (long)IDX(uidx, mclamp >> 1, is64) * BATCH + (mclamp & 1);
    const __half* __restrict__ aptr = g_nodes_h + gath * IN_DIM + ak;
    const __half* __restrict__ bptr =
        g_WhT + (long)which * IN_DIM * OUT_DIM + (long)(tile_n + ar) * IN_DIM + ak;

    const uint32_t sb = smem_u32(smh);
    const uint32_t a_sm = sb + (ar * AH_STRIDE + ak) * 2;
    const uint32_t b_sm = a_sm + 2 * AH_HALVES * 2;

    const int wid = t >> 5, lane = t & 31;
    const int g = lane >> 2, tg = lane & 3;
    const int wm = (wid >> 2) * 32;
    const int wn = (wid & 3) * 32;

    float acc[2][4][4];
#pragma unroll
    for (int i = 0; i < 2; i++)
#pragma unroll
        for (int j = 0; j < 4; j++)
#pragma unroll
            for (int q = 0; q < 4; q++) acc[i][j][q] = 0.f;

    CP_ASYNC16(a_sm, aptr);
    CP_ASYNC16(b_sm, bptr);
    CP_COMMIT();

    for (int c = 0; c < 8; c++) {
        const int buf = c & 1;
        if (c < 7) {
            const int kb = (c + 1) * 32;
            const uint32_t off = (buf ^ 1) * (AH_HALVES * 2);
            CP_ASYNC16(a_sm + off, aptr + kb);
            CP_ASYNC16(b_sm + off, bptr + kb);
            CP_COMMIT();
            CP_WAIT1();
        } else {
            CP_WAIT0();
        }
        __syncthreads();

        const __half* __restrict__ A = smh + buf * AH_HALVES;
        const __half* __restrict__ B = smh + (2 + buf) * AH_HALVES;
#pragma unroll
        for (int k0 = 0; k0 < 32; k0 += 16) {
            uint32_t a0[4], a1[4];
            const int kc = k0 + 2 * tg;
            a0[0] = *reinterpret_cast<const uint32_t*>(A + (wm + g)      * AH_STRIDE + kc);
            a0[1] = *reinterpret_cast<const uint32_t*>(A + (wm + g + 8)  * AH_STRIDE + kc);
            a0[2] = *reinterpret_cast<const uint32_t*>(A + (wm + g)      * AH_STRIDE + kc + 8);
            a0[3] = *reinterpret_cast<const uint32_t*>(A + (wm + g + 8)  * AH_STRIDE + kc + 8);
            a1[0] = *reinterpret_cast<const uint32_t*>(A + (wm + 16 + g)     * AH_STRIDE + kc);
            a1[1] = *reinterpret_cast<const uint32_t*>(A + (wm + 16 + g + 8) * AH_STRIDE + kc);
            a1[2] = *reinterpret_cast<const uint32_t*>(A + (wm + 16 + g)     * AH_STRIDE + kc + 8);
            a1[3] = *reinterpret_cast<const uint32_t*>(A + (wm + 16 + g + 8) * AH_STRIDE + kc + 8);
#pragma unroll
            for (int bx = 0; bx < 4; bx++) {
                const int nrow = wn + bx * 8 + g;
                uint32_t b0 = *reinterpret_cast<const uint32_t*>(B + nrow * AH_STRIDE + kc);
                uint32_t b1 = *reinterpret_cast<const uint32_t*>(B + nrow * AH_STRIDE + kc + 8);
                mma_f16(acc[0][bx], a0, b0, b1);
                mma_f16(acc[1][bx], a1, b0, b1);
            }
        }
        __syncthreads();
    }

    // ---- epilogue ----
    const int slot = blockIdx.y * 4 + (wid & 3);
#pragma unroll
    for (int am = 0; am < 2; am++) {
        const int m0 = tile_m + wm + am * 16 + g;
        const int m1 = m0 + 8;
        float d0 = 0.f, d1 = 0.f;
#pragma unroll
        for (int bx = 0; bx < 4; bx++) {
            const int col = tile_n + wn + bx * 8 + tg * 2;
            const float bi0 = bias[col], bi1 = bias[col + 1];
            float v00 = acc[am][bx][0] + bi0, v01 = acc[am][bx][1] + bi1;
            float v10 = acc[am][bx][2] + bi0, v11 = acc[am][bx][3] + bi1;
            if (which == 0) {
                const float wa0 = Wa[col], wa1 = Wa[col + 1];
                d0 = fmaf(v00, wa0, fmaf(v01, wa1, d0));
                d1 = fmaf(v10, wa0, fmaf(v11, wa1, d1));
                if (m0 < M)
                    *reinterpret_cast<float2*>(g_src_proj + (long)m0 * OUT_DIM + col) =
                        make_float2(v00, v01);
                if (m1 < M)
                    *reinterpret_cast<float2*>(g_src_proj + (long)m1 * OUT_DIM + col) =
                        make_float2(v10, v11);
            } else {
                if (m0 < M)
                    *reinterpret_cast<__half2*>(g_vals_h + (long)m0 * OUT_DIM + col) =
                        __floats2half2_rn(v00, v01);
                if (m1 < M)
                    *reinterpret_cast<__half2*>(g_vals_h + (long)m1 * OUT_DIM + col) =
                        __floats2half2_rn(v10, v11);
            }
        }
        if (which == 0) {
            d0 += __shfl_xor_sync(0xFFFFFFFFu, d0, 1);
            d0 += __shfl_xor_sync(0xFFFFFFFFu, d0, 2);
            d1 += __shfl_xor_sync(0xFFFFFFFFu, d1, 1);
            d1 += __shfl_xor_sync(0xFFFFFFFFu, d1, 2);
            if (tg == 0) {
                if (m0 < M) g_sdot_part[slot][m0] = d0;
                if (m1 < M) g_sdot_part[slot][m1] = d1;
            }
        }
    }
}

// ---------------- edge: ex + segment bounds (sorted sid) --------------------
__global__ void k_edge(const void* __restrict__ sidp, const void* __restrict__ tidp,
                       const float* __restrict__ ba, int E) {
    int e = blockIdx.x * blockDim.x + threadIdx.x;
    if (e >= E) return;
    const int is64 = g_idx64;
    const int s = IDX(sidp, e, is64);
    if (e == 0 || IDX(sidp, e - 1, is64) != s) g_seg_start[s] = e;
    if (e == E - 1 || IDX(sidp, e + 1, is64) != s) g_seg_end[s] = e + 1;
    const int tg = IDX(tidp, e, is64);
    const float b0 = ba[0];
#pragma unroll
    for (int b = 0; b < BATCH; b++) {
        float sd = ((g_sdot_part[0][s * 2 + b] + g_sdot_part[1][s * 2 + b])
                  + (g_sdot_part[2][s * 2 + b] + g_sdot_part[3][s * 2 + b]))
                 + ((g_sdot_part[4][s * 2 + b] + g_sdot_part[5][s * 2 + b])
                  + (g_sdot_part[6][s * 2 + b] + g_sdot_part[7][s * 2 + b]));
        float sc = sd + g_tdot[tg * 2 + b] + b0;
        sc = (sc >= 0.f) ? sc : SLOPE * sc;
        sc = fminf(2.f, fmaxf(-2.f, sc));
        g_ex[e * 2 + b] = expf(sc);
    }
}

// deterministic segment-sum of ex
__global__ void k_denom(int Ns) {
    int i = blockIdx.x * blockDim.x + threadIdx.x;
    if (i >= Ns * BATCH) return;
    int n = i >> 1, b = i & 1;
    int s0 = g_seg_start[n], s1 = g_seg_end[n];
    float d = 0.f;
    for (int e = s0; e < s1; e++) d += g_ex[e * 2 + b];
    g_denom[i] = d;
}

// ---------------- aggregation: 2 nodes / block, half2 loads, inline pack ----
// out[n,b,:] = src_proj[n,b,:] + sum_{e in seg(n)} alpha[tid[e],b] * vals[tid[tid[e]],b,:]
__global__ __launch_bounds__(512) void k_agg(const void* __restrict__ sidp,
                                             const void* __restrict__ tidp,
                                             float* __restrict__ out, int Ns) {
    __shared__ float2 ws[2][16];
    __shared__ int rs[2][16];
    const int t = threadIdx.x;
    const int sub = t >> 8;            // which node in this block
    const int rest = t & 255;
    const int b = rest >> 7;           // batch
    const int o2 = rest & 127;         // half2 column index
    const int is64 = g_idx64;

    const int n = blockIdx.x * 2 + sub;
    const bool valid = (n < Ns);
    const int n0 = blockIdx.x * 2;
    const int n1 = min(n0 + 1, Ns - 1);
    const int cmax = max(g_seg_end[n0] - g_seg_start[n0],
                         g_seg_end[n1] - g_seg_start[n1]);
    const int s0 = valid ? g_seg_start[n] : 0;
    const int s1 = valid ? g_seg_end[n] : 0;

    const long outbase = ((long)n * BATCH + b) * OUT_DIM + 2 * o2;
    float2 acc = valid ? *reinterpret_cast<const float2*>(g_src_proj + outbase)
                       : make_float2(0.f, 0.f);
    float2 acc2 = make_float2(0.f, 0.f);

    for (int base = 0; base < cmax; base += 16) {
        if (rest < 16) {
            int e = s0 + base + rest;
            if (e < s1) {
                int j = IDX(tidp, e, is64);           // edge index (faithful bug)
                int sj = IDX(sidp, j, is64);
                ws[sub][rest] = make_float2(g_ex[j * 2 + 0] / g_denom[sj * 2 + 0],
                                            g_ex[j * 2 + 1] / g_denom[sj * 2 + 1]);
                rs[sub][rest] = IDX(tidp, j, is64);   // tid[tid[e]]
            } else {
                ws[sub][rest] = make_float2(0.f, 0.f);
                rs[sub][rest] = 0;
            }
        }
        __syncthreads();
        const int lim = min(16, s1 - s0 - base);
        if (lim == 16) {
#pragma unroll
            for (int i = 0; i < 16; i += 2) {
                float2 wA2 = ws[sub][i];
                float2 wB2 = ws[sub][i + 1];
                float wA = b ? wA2.y : wA2.x;
                float wB = b ? wB2.y : wB2.x;
                __half2 hA = *reinterpret_cast<const __half2*>(
                    g_vals_h + (((long)rs[sub][i] << 1) + b) * OUT_DIM + 2 * o2);
                __half2 hB = *reinterpret_cast<const __half2*>(
                    g_vals_h + (((long)rs[sub][i + 1] << 1) + b) * OUT_DIM + 2 * o2);
                float2 vA = __half22float2(hA);
                float2 vB = __half22float2(hB);
                acc.x  = fmaf(wA, vA.x, acc.x);
                acc.y  = fmaf(wA, vA.y, acc.y);
                acc2.x = fmaf(wB, vB.x, acc2.x);
                acc2.y = fmaf(wB, vB.y, acc2.y);
            }
        } else {
            for (int i = 0; i < lim; i++) {
                float2 w2 = ws[sub][i];
                float w = b ? w2.y : w2.x;
                __half2 h = *reinterpret_cast<const __half2*>(
                    g_vals_h + (((long)rs[sub][i] << 1) + b) * OUT_DIM + 2 * o2);
                float2 v = __half22float2(h);
                acc.x = fmaf(w, v.x, acc.x);
                acc.y = fmaf(w, v.y, acc.y);
            }
        }
        __syncthreads();
    }
    if (valid) {
        acc.x += acc2.x;
        acc.y += acc2.y;
        *reinterpret_cast<float2*>(out + outbase) = acc;
    }
}

extern "C" void kernel_launch(void* const* d_in, const int* in_sizes, int n_in,
                              void* d_out, int out_size) {
    const float* nodes = (const float*)d_in[0];
    const float* Ws    = (const float*)d_in[1];
    const float* bs    = (const float*)d_in[2];
    const float* Wt    = (const float*)d_in[3];
    const float* bt    = (const float*)d_in[4];
    const float* Wv    = (const float*)d_in[5];
    const float* bv    = (const float*)d_in[6];
    const float* Wa    = (const float*)d_in[7];
    const float* ba    = (const float*)d_in[8];
    const void* usrc   = d_in[9];
    const void* utgt   = d_in[10];
    const void* sidp   = d_in[11];
    const void* tidp   = d_in[12];

    const int Ns = in_sizes[9];
    const int Nt = in_sizes[10];
    const int E  = in_sizes[11];
    const int ntot = in_sizes[0];
    float* out = (float*)d_out;

    static int smem_set = 0;
    if (!smem_set) {
        cudaFuncSetAttribute(k_gemm_mma, cudaFuncAttributeMaxDynamicSharedMemorySize,
                             SMH_TOTAL * 2);
        smem_set = 1;
    }

    const int Ms = Ns * BATCH;
    const int Mt = Nt * BATCH;
    const int NC = (ntot + 2047) / 2048;

    k_prep<<<33 + NC + 128, 256>>>(usrc, Wt, bt, Wa, nodes, Ws, Wv, ntot, NC);
    k_tdot<<<(Mt * 32 + 255) / 256, 256>>>(nodes, utgt, Mt);

    const int Mmax = (Ms > Mt) ? Ms : Mt;
    dim3 gg((Mmax + 127) / 128, OUT_DIM / 128, 2);
    k_gemm_mma<<<gg, 512, SMH_TOTAL * 2>>>(usrc, utgt, bs, bv, Wa, Ms, Mt);

    k_edge<<<(E + 255) / 256, 256>>>(sidp, tidp, ba, E);
    k_denom<<<(Ns * BATCH + 255) / 256, 256>>>(Ns);

    k_agg<<<(Ns + 1) / 2, 512>>>(sidp, tidp, out, Ns);
}

// round 12
// speedup vs baseline: 1.4897x; 1.0239x over previous
#include <cuda_runtime.h>
#include <cuda_fp16.h>
#include <math.h>
#include <stdint.h>

#define IN_DIM 256
#define OUT_DIM 256
#define BATCH 2
#define MAXN 10240
#define MAXE 163840
#define SLOPE 0.2f

// ---------------- scratch (static device globals; no allocation) ----------
static __device__ float  g_src_proj[MAXN * BATCH * OUT_DIM];    // 20 MB
static __device__ __half g_vals_h[MAXN * BATCH * OUT_DIM];      // 10 MB
static __device__ __half g_nodes_h[MAXN * BATCH * IN_DIM];      // 10 MB
static __device__ __half g_WhT[2 * IN_DIM * OUT_DIM];           // W^T fp16
static __device__ float  g_sdot_part[8][MAXN * BATCH];
static __device__ float  g_tdot[MAXN * BATCH];
static __device__ float  g_denom[MAXN * BATCH];
static __device__ float  g_ex[MAXE * BATCH];
static __device__ int    g_seg_start[MAXN];
static __device__ int    g_seg_end[MAXN];
static __device__ float  g_wta[IN_DIM];
static __device__ float  g_ct;
static __device__ int    g_idx64;

// ---------------- index dtype handling -------------------------------------
__device__ __forceinline__ int IDX(const void* p, int i, int is64) {
    if (is64) return (int)(((const long long*)p)[i]);
    return ((const int*)p)[i];
}

// ---------------- fused prep: detect + ct + wta + fp16 conv + seg bounds ----
// block 0                    : detect + ct
// blocks [1, 33)             : wta (warp per k)
// blocks [33, 33+NC)         : nodes fp32 -> fp16
// blocks [33+NC, +128)       : W transpose+convert
// blocks [33+NC+128, +NE)    : segment bounds from sorted sid
__global__ void k_prep(const void* __restrict__ usrc,
                       const float* __restrict__ Wt, const float* __restrict__ bt,
                       const float* __restrict__ Wa,
                       const float* __restrict__ nodes,
                       const float* __restrict__ Ws, const float* __restrict__ Wv,
                       const void* __restrict__ sidp,
                       int ntot, int NC, int E) {
    const int bid = blockIdx.x;
    const int t = threadIdx.x;
    if (bid == 0) {
        if (t == 0) {
            const int* p = (const int*)usrc;
            g_idx64 = (p[1] == 0 && p[3] == 0) ? 1 : 0;
        }
        __shared__ float red[256];
        red[t] = bt[t] * Wa[OUT_DIM + t];
        __syncthreads();
        for (int st = 128; st > 0; st >>= 1) {
            if (t < st) red[t] += red[t + st];
            __syncthreads();
        }
        if (t == 0) g_ct = red[0];
    } else if (bid < 33) {
        const int k = (bid - 1) * 8 + (t >> 5);
        const int lane = t & 31;
        const float* wrow = Wt + (long)k * OUT_DIM;
        float s = 0.f;
#pragma unroll
        for (int o = lane; o < OUT_DIM; o += 32) s = fmaf(wrow[o], Wa[OUT_DIM + o], s);
#pragma unroll
        for (int st = 16; st; st >>= 1) s += __shfl_xor_sync(0xFFFFFFFFu, s, st);
        if (lane == 0) g_wta[k] = s;
    } else if (bid < 33 + NC) {
        long idx = (long)(bid - 33) * 2048 + t * 8;
        if (idx + 8 <= ntot) {
            float4 v0 = *reinterpret_cast<const float4*>(nodes + idx);
            float4 v1 = *reinterpret_cast<const float4*>(nodes + idx + 4);
            __half2 h0 = __floats2half2_rn(v0.x, v0.y);
            __half2 h1 = __floats2half2_rn(v0.z, v0.w);
            __half2 h2 = __floats2half2_rn(v1.x, v1.y);
            __half2 h3 = __floats2half2_rn(v1.z, v1.w);
            uint4 o;
            o.x = *reinterpret_cast<uint32_t*>(&h0);
            o.y = *reinterpret_cast<uint32_t*>(&h1);
            o.z = *reinterpret_cast<uint32_t*>(&h2);
            o.w = *reinterpret_cast<uint32_t*>(&h3);
            *reinterpret_cast<uint4*>(g_nodes_h + idx) = o;
        }
    } else if (bid < 33 + NC + 128) {
        const int j = bid - 33 - NC;          // 0..127
        const int which = j >> 6;
        const float* __restrict__ W = which ? Wv : Ws;
        const int n = (j & 63) * 4 + (t >> 6);
        const int k = (t & 63) * 4;
        __half* dst = g_WhT + (long)which * IN_DIM * OUT_DIM + (long)n * IN_DIM + k;
#pragma unroll
        for (int q = 0; q < 4; q++)
            dst[q] = __float2half_rn(W[(long)(k + q) * OUT_DIM + n]);
    } else {
        const int e = (bid - 33 - NC - 128) * 256 + t;
        if (e < E) {
            const int is64 = g_idx64;   // NOTE: detect runs in block 0 of SAME launch;
            // blocks are independent — use direct check instead of g_idx64:
            const int* p = (const int*)usrc;
            const int my64 = (p[1] == 0 && p[3] == 0) ? 1 : 0;
            (void)is64;
            const int s = IDX(sidp, e, my64);
            if (e == 0 || IDX(sidp, e - 1, my64) != s) g_seg_start[s] = e;
            if (e == E - 1 || IDX(sidp, e + 1, my64) != s) g_seg_end[s] = e + 1;
        }
    }
}

// ---------------- tdot (warp per row, fp32 nodes) ---------------------------
__global__ void k_tdot(const float* __restrict__ nodes, const void* __restrict__ utgt,
                       int Mt) {
    int m = (blockIdx.x * blockDim.x + threadIdx.x) >> 5;
    int lane = threadIdx.x & 31;
    if (m >= Mt) return;
    int is64 = g_idx64;
    int nidx = m >> 1, b = m & 1;
    long gidx = (long)IDX(utgt, nidx, is64) * BATCH + b;
    const float* row = nodes + gidx * IN_DIM;
    float s = 0.f;
#pragma unroll
    for (int o = lane; o < IN_DIM; o += 32) s = fmaf(row[o], g_wta[o], s);
#pragma unroll
    for (int st = 16; st; st >>= 1) s += __shfl_xor_sync(0xFFFFFFFFu, s, st);
    if (lane == 0) g_tdot[m] = s + g_ct;
}

// ---------------- fp16 mma.sync gathered GEMM (512 threads, 16 warps) -------
#define AH_STRIDE 40
#define AH_HALVES (128 * AH_STRIDE)
#define SMH_TOTAL (4 * AH_HALVES)

__device__ __forceinline__ uint32_t smem_u32(const void* p) {
    uint32_t a;
    asm("{ .reg .u64 t; cvta.to.shared.u64 t, %1; cvt.u32.u64 %0, t; }" : "=r"(a) : "l"(p));
    return a;
}
#define CP_ASYNC16(smaddr, gptr) \
    asm volatile("cp.async.ca.shared.global [%0], [%1], 16;" :: "r"(smaddr), "l"(gptr))
#define CP_COMMIT() asm volatile("cp.async.commit_group;" ::: "memory")
#define CP_WAIT1()  asm volatile("cp.async.wait_group 1;" ::: "memory")
#define CP_WAIT0()  asm volatile("cp.async.wait_group 0;" ::: "memory")

__device__ __forceinline__ void mma_f16(float* c, const uint32_t* a, uint32_t b0, uint32_t b1) {
    asm volatile(
        "mma.sync.aligned.m16n8k16.row.col.f32.f16.f16.f32 "
        "{%0,%1,%2,%3}, {%4,%5,%6,%7}, {%8,%9}, {%0,%1,%2,%3};"
        : "+f"(c[0]), "+f"(c[1]), "+f"(c[2]), "+f"(c[3])
        : "r"(a[0]), "r"(a[1]), "r"(a[2]), "r"(a[3]), "r"(b0), "r"(b1));
}

__global__ __launch_bounds__(512, 2) void k_gemm_mma(
    const void* __restrict__ usrc, const void* __restrict__ utgt,
    const float* __restrict__ bs, const float* __restrict__ bv,
    const float* __restrict__ Wa, int Ms, int Mt)
{
    extern __shared__ __half smh[];
    const int which = blockIdx.z;
    const void* __restrict__ uidx = which ? utgt : usrc;
    const float* __restrict__ bias = which ? bv : bs;
    const int M = which ? Mt : Ms;

    const int t = threadIdx.x;
    const int tile_m = blockIdx.x * 128;
    const int tile_n = blockIdx.y * 128;
    if (tile_m >= M) return;
    const int is64 = g_idx64;

    const int ar = t >> 2;
    const int ak = (t & 3) * 8;
    const int mclamp = min(tile_m + ar, M - 1);
    const long gath = (long)IDX(uidx, mclamp >> 1, is64) * BATCH + (mclamp & 1);
    const __half* __restrict__ aptr = g_nodes_h + gath * IN_DIM + ak;
    const __half* __restrict__ bptr =
        g_WhT + (long)which * IN_DIM * OUT_DIM + (long)(tile_n + ar) * IN_DIM + ak;

    const uint32_t sb = smem_u32(smh);
    const uint32_t a_sm = sb + (ar * AH_STRIDE + ak) * 2;
    const uint32_t b_sm = a_sm + 2 * AH_HALVES * 2;

    const int wid = t >> 5, lane = t & 31;
    const int g = lane >> 2, tg = lane & 3;
    const int wm = (wid >> 2) * 32;
    const int wn = (wid & 3) * 32;

    float acc[2][4][4];
#pragma unroll
    for (int i = 0; i < 2; i++)
#pragma unroll
        for (int j = 0; j < 4; j++)
#pragma unroll
            for (int q = 0; q < 4; q++) acc[i][j][q] = 0.f;

    CP_ASYNC16(a_sm, aptr);
    CP_ASYNC16(b_sm, bptr);
    CP_COMMIT();

    for (int c = 0; c < 8; c++) {
        const int buf = c & 1;
        if (c < 7) {
            const int kb = (c + 1) * 32;
            const uint32_t off = (buf ^ 1) * (AH_HALVES * 2);
            CP_ASYNC16(a_sm + off, aptr + kb);
            CP_ASYNC16(b_sm + off, bptr + kb);
            CP_COMMIT();
            CP_WAIT1();
        } else {
            CP_WAIT0();
        }
        __syncthreads();

        const __half* __restrict__ A = smh + buf * AH_HALVES;
        const __half* __restrict__ B = smh + (2 + buf) * AH_HALVES;
#pragma unroll
        for (int k0 = 0; k0 < 32; k0 += 16) {
            uint32_t a0[4], a1[4];
            const int kc = k0 + 2 * tg;
            a0[0] = *reinterpret_cast<const uint32_t*>(A + (wm + g)      * AH_STRIDE + kc);
            a0[1] = *reinterpret_cast<const uint32_t*>(A + (wm + g + 8)  * AH_STRIDE + kc);
            a0[2] = *reinterpret_cast<const uint32_t*>(A + (wm + g)      * AH_STRIDE + kc + 8);
            a0[3] = *reinterpret_cast<const uint32_t*>(A + (wm + g + 8)  * AH_STRIDE + kc + 8);
            a1[0] = *reinterpret_cast<const uint32_t*>(A + (wm + 16 + g)     * AH_STRIDE + kc);
            a1[1] = *reinterpret_cast<const uint32_t*>(A + (wm + 16 + g + 8) * AH_STRIDE + kc);
            a1[2] = *reinterpret_cast<const uint32_t*>(A + (wm + 16 + g)     * AH_STRIDE + kc + 8);
            a1[3] = *reinterpret_cast<const uint32_t*>(A + (wm + 16 + g + 8) * AH_STRIDE + kc + 8);
#pragma unroll
            for (int bx = 0; bx < 4; bx++) {
                const int nrow = wn + bx * 8 + g;
                uint32_t b0 = *reinterpret_cast<const uint32_t*>(B + nrow * AH_STRIDE + kc);
                uint32_t b1 = *reinterpret_cast<const uint32_t*>(B + nrow * AH_STRIDE + kc + 8);
                mma_f16(acc[0][bx], a0, b0, b1);
                mma_f16(acc[1][bx], a1, b0, b1);
            }
        }
        __syncthreads();
    }

    // ---- epilogue ----
    const int slot = blockIdx.y * 4 + (wid & 3);
#pragma unroll
    for (int am = 0; am < 2; am++) {
        const int m0 = tile_m + wm + am * 16 + g;
        const int m1 = m0 + 8;
        float d0 = 0.f, d1 = 0.f;
#pragma unroll
        for (int bx = 0; bx < 4; bx++) {
            const int col = tile_n + wn + bx * 8 + tg * 2;
            const float bi0 = bias[col], bi1 = bias[col + 1];
            float v00 = acc[am][bx][0] + bi0, v01 = acc[am][bx][1] + bi1;
            float v10 = acc[am][bx][2] + bi0, v11 = acc[am][bx][3] + bi1;
            if (which == 0) {
                const float wa0 = Wa[col], wa1 = Wa[col + 1];
                d0 = fmaf(v00, wa0, fmaf(v01, wa1, d0));
                d1 = fmaf(v10, wa0, fmaf(v11, wa1, d1));
                if (m0 < M)
                    *reinterpret_cast<float2*>(g_src_proj + (long)m0 * OUT_DIM + col) =
                        make_float2(v00, v01);
                if (m1 < M)
                    *reinterpret_cast<float2*>(g_src_proj + (long)m1 * OUT_DIM + col) =
                        make_float2(v10, v11);
            } else {
                if (m0 < M)
                    *reinterpret_cast<__half2*>(g_vals_h + (long)m0 * OUT_DIM + col) =
                        __floats2half2_rn(v00, v01);
                if (m1 < M)
                    *reinterpret_cast<__half2*>(g_vals_h + (long)m1 * OUT_DIM + col) =
                        __floats2half2_rn(v10, v11);
            }
        }
        if (which == 0) {
            d0 += __shfl_xor_sync(0xFFFFFFFFu, d0, 1);
            d0 += __shfl_xor_sync(0xFFFFFFFFu, d0, 2);
            d1 += __shfl_xor_sync(0xFFFFFFFFu, d1, 1);
            d1 += __shfl_xor_sync(0xFFFFFFFFu, d1, 2);
            if (tg == 0) {
                if (m0 < M) g_sdot_part[slot][m0] = d0;
                if (m1 < M) g_sdot_part[slot][m1] = d1;
            }
        }
    }
}

// ---------------- softmax: warp per source node ------------------------------
// lanes 0-15 load the 8 sdot partials (x2 batches), shuffle-reduce;
// each lane computes ex for its edges; warp-reduce denominators.
__global__ void k_softmax(const void* __restrict__ tidp,
                          const float* __restrict__ ba, int Ns) {
    const int w = (blockIdx.x * blockDim.x + threadIdx.x) >> 5;
    const int lane = threadIdx.x & 31;
    if (w >= Ns) return;
    const int is64 = g_idx64;
    const int s0 = g_seg_start[w], s1 = g_seg_end[w];

    // sdot partial reduction: lanes 0-7 -> batch 0, lanes 8-15 -> batch 1
    float p = 0.f;
    if (lane < 16) p = g_sdot_part[lane & 7][w * 2 + (lane >> 3)];
    p += __shfl_xor_sync(0xFFFFFFFFu, p, 1);
    p += __shfl_xor_sync(0xFFFFFFFFu, p, 2);
    p += __shfl_xor_sync(0xFFFFFFFFu, p, 4);
    const float sd0 = __shfl_sync(0xFFFFFFFFu, p, 0) + ba[0];
    const float sd1 = __shfl_sync(0xFFFFFFFFu, p, 8) + ba[0];

    float d0 = 0.f, d1 = 0.f;
    for (int e = s0 + lane; e < s1; e += 32) {
        int tg = IDX(tidp, e, is64);
        float sc0 = sd0 + g_tdot[tg * 2 + 0];
        float sc1 = sd1 + g_tdot[tg * 2 + 1];
        sc0 = (sc0 >= 0.f) ? sc0 : SLOPE * sc0;
        sc1 = (sc1 >= 0.f) ? sc1 : SLOPE * sc1;
        sc0 = fminf(2.f, fmaxf(-2.f, sc0));
        sc1 = fminf(2.f, fmaxf(-2.f, sc1));
        float e0 = expf(sc0), e1 = expf(sc1);
        g_ex[e * 2 + 0] = e0;
        g_ex[e * 2 + 1] = e1;
        d0 += e0;
        d1 += e1;
    }
#pragma unroll
    for (int st = 16; st; st >>= 1) {
        d0 += __shfl_xor_sync(0xFFFFFFFFu, d0, st);
        d1 += __shfl_xor_sync(0xFFFFFFFFu, d1, st);
    }
    if (lane == 0) {
        g_denom[w * 2 + 0] = d0;
        g_denom[w * 2 + 1] = d1;
    }
}

// ---------------- aggregation: 2 nodes / block, half2 loads, inline pack ----
__global__ __launch_bounds__(512) void k_agg(const void* __restrict__ sidp,
                                             const void* __restrict__ tidp,
                                             float* __restrict__ out, int Ns) {
    __shared__ float2 ws[2][16];
    __shared__ int rs[2][16];
    const int t = threadIdx.x;
    const int sub = t >> 8;
    const int rest = t & 255;
    const int b = rest >> 7;
    const int o2 = rest & 127;
    const int is64 = g_idx64;

    const int n = blockIdx.x * 2 + sub;
    const bool valid = (n < Ns);
    const int n0 = blockIdx.x * 2;
    const int n1 = min(n0 + 1, Ns - 1);
    const int cmax = max(g_seg_end[n0] - g_seg_start[n0],
                         g_seg_end[n1] - g_seg_start[n1]);
    const int s0 = valid ? g_seg_start[n] : 0;
    const int s1 = valid ? g_seg_end[n] : 0;

    const long outbase = ((long)n * BATCH + b) * OUT_DIM + 2 * o2;
    float2 acc = valid ? *reinterpret_cast<const float2*>(g_src_proj + outbase)
                       : make_float2(0.f, 0.f);
    float2 acc2 = make_float2(0.f, 0.f);

    for (int base = 0; base < cmax; base += 16) {
        if (rest < 16) {
            int e = s0 + base + rest;
            if (e < s1) {
                int j = IDX(tidp, e, is64);
                int sj = IDX(sidp, j, is64);
                ws[sub][rest] = make_float2(g_ex[j * 2 + 0] / g_denom[sj * 2 + 0],
                                            g_ex[j * 2 + 1] / g_denom[sj * 2 + 1]);
                rs[sub][rest] = IDX(tidp, j, is64);
            } else {
                ws[sub][rest] = make_float2(0.f, 0.f);
                rs[sub][rest] = 0;
            }
        }
        __syncthreads();
        const int lim = min(16, s1 - s0 - base);
        if (lim == 16) {
#pragma unroll
            for (int i = 0; i < 16; i += 2) {
                float2 wA2 = ws[sub][i];
                float2 wB2 = ws[sub][i + 1];
                float wA = b ? wA2.y : wA2.x;
                float wB = b ? wB2.y : wB2.x;
                __half2 hA = *reinterpret_cast<const __half2*>(
                    g_vals_h + (((long)rs[sub][i] << 1) + b) * OUT_DIM + 2 * o2);
                __half2 hB = *reinterpret_cast<const __half2*>(
                    g_vals_h + (((long)rs[sub][i + 1] << 1) + b) * OUT_DIM + 2 * o2);
                float2 vA = __half22float2(hA);
                float2 vB = __half22float2(hB);
                acc.x  = fmaf(wA, vA.x, acc.x);
                acc.y  = fmaf(wA, vA.y, acc.y);
                acc2.x = fmaf(wB, vB.x, acc2.x);
                acc2.y = fmaf(wB, vB.y, acc2.y);
            }
        } else {
            for (int i = 0; i < lim; i++) {
                float2 w2 = ws[sub][i];
                float w = b ? w2.y : w2.x;
                __half2 h = *reinterpret_cast<const __half2*>(
                    g_vals_h + (((long)rs[sub][i] << 1) + b) * OUT_DIM + 2 * o2);
                float2 v = __half22float2(h);
                acc.x = fmaf(w, v.x, acc.x);
                acc.y = fmaf(w, v.y, acc.y);
            }
        }
        __syncthreads();
    }
    if (valid) {
        acc.x += acc2.x;
        acc.y += acc2.y;
        *reinterpret_cast<float2*>(out + outbase) = acc;
    }
}

extern "C" void kernel_launch(void* const* d_in, const int* in_sizes, int n_in,
                              void* d_out, int out_size) {
    const float* nodes = (const float*)d_in[0];
    const float* Ws    = (const float*)d_in[1];
    const float* bs    = (const float*)d_in[2];
    const float* Wt    = (const float*)d_in[3];
    const float* bt    = (const float*)d_in[4];
    const float* Wv    = (const float*)d_in[5];
    const float* bv    = (const float*)d_in[6];
    const float* Wa    = (const float*)d_in[7];
    const float* ba    = (const float*)d_in[8];
    const void* usrc   = d_in[9];
    const void* utgt   = d_in[10];
    const void* sidp   = d_in[11];
    const void* tidp   = d_in[12];

    const int Ns = in_sizes[9];
    const int Nt = in_sizes[10];
    const int E  = in_sizes[11];
    const int ntot = in_sizes[0];
    float* out = (float*)d_out;

    static int smem_set = 0;
    if (!smem_set) {
        cudaFuncSetAttribute(k_gemm_mma, cudaFuncAttributeMaxDynamicSharedMemorySize,
                             SMH_TOTAL * 2);
        smem_set = 1;
    }

    const int Ms = Ns * BATCH;
    const int Mt = Nt * BATCH;
    const int NC = (ntot + 2047) / 2048;
    const int NE = (E + 255) / 256;

    k_prep<<<33 + NC + 128 + NE, 256>>>(usrc, Wt, bt, Wa, nodes, Ws, Wv, sidp,
                                        ntot, NC, E);
    k_tdot<<<(Mt * 32 + 255) / 256, 256>>>(nodes, utgt, Mt);

    const int Mmax = (Ms > Mt) ? Ms : Mt;
    dim3 gg((Mmax + 127) / 128, OUT_DIM / 128, 2);
    k_gemm_mma<<<gg, 512, SMH_TOTAL * 2>>>(usrc, utgt, bs, bv, Wa, Ms, Mt);

    k_softmax<<<(Ns * 32 + 255) / 256, 256>>>(tidp, ba, Ns);

    k_agg<<<(Ns + 1) / 2, 512>>>(sidp, tidp, out, Ns);
}

// round 13
// speedup vs baseline: 1.5295x; 1.0267x over previous
#include <cuda_runtime.h>
#include <cuda_fp16.h>
#include <math.h>
#include <stdint.h>

#define IN_DIM 256
#define OUT_DIM 256
#define BATCH 2
#define MAXN 10240
#define MAXE 163840
#define SLOPE 0.2f

// ---------------- scratch (static device globals; no allocation) ----------
static __device__ float  g_src_proj[MAXN * BATCH * OUT_DIM];    // 20 MB
static __device__ __half g_vals_h[MAXN * BATCH * OUT_DIM];      // 10 MB
static __device__ __half g_nodes_h[MAXN * BATCH * IN_DIM];      // 10 MB
static __device__ __half g_WhT[2 * IN_DIM * OUT_DIM];           // W^T fp16
static __device__ float  g_sdot_part[8][MAXN * BATCH];
static __device__ float  g_tdot[MAXN * BATCH];
static __device__ float  g_denom[MAXN * BATCH];
static __device__ float  g_ex[MAXE * BATCH];
static __device__ int    g_seg_start[MAXN];
static __device__ int    g_seg_end[MAXN];
static __device__ float  g_wta[IN_DIM];
static __device__ float  g_ct;
static __device__ int    g_idx64;

// ---------------- index dtype handling -------------------------------------
__device__ __forceinline__ int IDX(const void* p, int i, int is64) {
    if (is64) return (int)(((const long long*)p)[i]);
    return ((const int*)p)[i];
}

// ---------------- fused prep: detect + ct + wta + fp16 conv + seg bounds ----
__global__ void k_prep(const void* __restrict__ usrc,
                       const float* __restrict__ Wt, const float* __restrict__ bt,
                       const float* __restrict__ Wa,
                       const float* __restrict__ nodes,
                       const float* __restrict__ Ws, const float* __restrict__ Wv,
                       const void* __restrict__ sidp,
                       int ntot, int NC, int E) {
    const int bid = blockIdx.x;
    const int t = threadIdx.x;
    if (bid == 0) {
        if (t == 0) {
            const int* p = (const int*)usrc;
            g_idx64 = (p[1] == 0 && p[3] == 0) ? 1 : 0;
        }
        __shared__ float red[256];
        red[t] = bt[t] * Wa[OUT_DIM + t];
        __syncthreads();
        for (int st = 128; st > 0; st >>= 1) {
            if (t < st) red[t] += red[t + st];
            __syncthreads();
        }
        if (t == 0) g_ct = red[0];
    } else if (bid < 33) {
        const int k = (bid - 1) * 8 + (t >> 5);
        const int lane = t & 31;
        const float* wrow = Wt + (long)k * OUT_DIM;
        float s = 0.f;
#pragma unroll
        for (int o = lane; o < OUT_DIM; o += 32) s = fmaf(wrow[o], Wa[OUT_DIM + o], s);
#pragma unroll
        for (int st = 16; st; st >>= 1) s += __shfl_xor_sync(0xFFFFFFFFu, s, st);
        if (lane == 0) g_wta[k] = s;
    } else if (bid < 33 + NC) {
        long idx = (long)(bid - 33) * 2048 + t * 8;
        if (idx + 8 <= ntot) {
            float4 v0 = *reinterpret_cast<const float4*>(nodes + idx);
            float4 v1 = *reinterpret_cast<const float4*>(nodes + idx + 4);
            __half2 h0 = __floats2half2_rn(v0.x, v0.y);
            __half2 h1 = __floats2half2_rn(v0.z, v0.w);
            __half2 h2 = __floats2half2_rn(v1.x, v1.y);
            __half2 h3 = __floats2half2_rn(v1.z, v1.w);
            uint4 o;
            o.x = *reinterpret_cast<uint32_t*>(&h0);
            o.y = *reinterpret_cast<uint32_t*>(&h1);
            o.z = *reinterpret_cast<uint32_t*>(&h2);
            o.w = *reinterpret_cast<uint32_t*>(&h3);
            *reinterpret_cast<uint4*>(g_nodes_h + idx) = o;
        }
    } else if (bid < 33 + NC + 128) {
        const int j = bid - 33 - NC;          // 0..127
        const int which = j >> 6;
        const float* __restrict__ W = which ? Wv : Ws;
        const int n = (j & 63) * 4 + (t >> 6);
        const int k = (t & 63) * 4;
        __half* dst = g_WhT + (long)which * IN_DIM * OUT_DIM + (long)n * IN_DIM + k;
#pragma unroll
        for (int q = 0; q < 4; q++)
            dst[q] = __float2half_rn(W[(long)(k + q) * OUT_DIM + n]);
    } else {
        const int e = (bid - 33 - NC - 128) * 256 + t;
        if (e < E) {
            const int* p = (const int*)usrc;
            const int my64 = (p[1] == 0 && p[3] == 0) ? 1 : 0;
            const int s = IDX(sidp, e, my64);
            if (e == 0 || IDX(sidp, e - 1, my64) != s) g_seg_start[s] = e;
            if (e == E - 1 || IDX(sidp, e + 1, my64) != s) g_seg_end[s] = e + 1;
        }
    }
}

// ---------------- fp16 mma.sync gathered GEMM (3-stage, tdot fused) ---------
#define AH_STRIDE 40
#define AH_HALVES (128 * AH_STRIDE)          // halves per A (or B) stage
#define NSTAGE 3
#define SMH_BYTES (2 * NSTAGE * AH_HALVES * 2)   // 61440 B

__device__ __forceinline__ uint32_t smem_u32(const void* p) {
    uint32_t a;
    asm("{ .reg .u64 t; cvta.to.shared.u64 t, %1; cvt.u32.u64 %0, t; }" : "=r"(a) : "l"(p));
    return a;
}
#define CP_ASYNC16(smaddr, gptr) \
    asm volatile("cp.async.ca.shared.global [%0], [%1], 16;" :: "r"(smaddr), "l"(gptr))
#define CP_COMMIT() asm volatile("cp.async.commit_group;" ::: "memory")
#define CP_WAIT2()  asm volatile("cp.async.wait_group 2;" ::: "memory")
#define CP_WAIT1()  asm volatile("cp.async.wait_group 1;" ::: "memory")
#define CP_WAIT0()  asm volatile("cp.async.wait_group 0;" ::: "memory")

__device__ __forceinline__ void mma_f16(float* c, const uint32_t* a, uint32_t b0, uint32_t b1) {
    asm volatile(
        "mma.sync.aligned.m16n8k16.row.col.f32.f16.f16.f32 "
        "{%0,%1,%2,%3}, {%4,%5,%6,%7}, {%8,%9}, {%0,%1,%2,%3};"
        : "+f"(c[0]), "+f"(c[1]), "+f"(c[2]), "+f"(c[3])
        : "r"(a[0]), "r"(a[1]), "r"(a[2]), "r"(a[3]), "r"(b0), "r"(b1));
}

__global__ __launch_bounds__(512, 2) void k_gemm_mma(
    const void* __restrict__ usrc, const void* __restrict__ utgt,
    const float* __restrict__ bs, const float* __restrict__ bv,
    const float* __restrict__ Wa, int Ms, int Mt)
{
    extern __shared__ __half smh[];
    const int which = blockIdx.z;
    const void* __restrict__ uidx = which ? utgt : usrc;
    const float* __restrict__ bias = which ? bv : bs;
    const int M = which ? Mt : Ms;

    const int t = threadIdx.x;
    const int tile_m = blockIdx.x * 128;
    const int tile_n = blockIdx.y * 128;
    if (tile_m >= M) return;
    const int is64 = g_idx64;

    const int ar = t >> 2;
    const int ak = (t & 3) * 8;
    const int mclamp = min(tile_m + ar, M - 1);
    const long gath = (long)IDX(uidx, mclamp >> 1, is64) * BATCH + (mclamp & 1);
    const __half* __restrict__ aptr = g_nodes_h + gath * IN_DIM + ak;
    const __half* __restrict__ bptr =
        g_WhT + (long)which * IN_DIM * OUT_DIM + (long)(tile_n + ar) * IN_DIM + ak;

    const uint32_t sb = smem_u32(smh);
    const uint32_t a_sm = sb + (ar * AH_STRIDE + ak) * 2;
    const uint32_t b_sm = a_sm + NSTAGE * AH_HALVES * 2;

    const int wid = t >> 5, lane = t & 31;
    const int g = lane >> 2, tg = lane & 3;
    const int wm = (wid >> 2) * 32;
    const int wn = (wid & 3) * 32;

    float acc[2][4][4];
#pragma unroll
    for (int i = 0; i < 2; i++)
#pragma unroll
        for (int j = 0; j < 4; j++)
#pragma unroll
            for (int q = 0; q < 4; q++) acc[i][j][q] = 0.f;

    // prologue: stages 0 and 1
    CP_ASYNC16(a_sm, aptr);
    CP_ASYNC16(b_sm, bptr);
    CP_COMMIT();
    CP_ASYNC16(a_sm + AH_HALVES * 2, aptr + 32);
    CP_ASYNC16(b_sm + AH_HALVES * 2, bptr + 32);
    CP_COMMIT();

    float tacc = 0.f;   // fused tdot partial (which==1)

    for (int c = 0; c < 8; c++) {
        const int buf = c % 3;
        if (c < 6) {
            const int kb = (c + 2) * 32;
            const uint32_t off = ((c + 2) % 3) * (AH_HALVES * 2);
            CP_ASYNC16(a_sm + off, aptr + kb);
            CP_ASYNC16(b_sm + off, bptr + kb);
            CP_COMMIT();
            CP_WAIT2();
        } else if (c == 6) {
            CP_WAIT1();
        } else {
            CP_WAIT0();
        }
        __syncthreads();

        const __half* __restrict__ A = smh + buf * AH_HALVES;
        const __half* __restrict__ B = smh + (NSTAGE + buf) * AH_HALVES;

        if (which) {
            // fused tdot: this thread's 8 halves of its A row for this chunk
            const __half* ap = A + ar * AH_STRIDE + ak;
            const float* wp = g_wta + c * 32 + ak;
#pragma unroll
            for (int j = 0; j < 8; j++)
                tacc = fmaf(__half2float(ap[j]), wp[j], tacc);
        }

#pragma unroll
        for (int k0 = 0; k0 < 32; k0 += 16) {
            uint32_t a0[4], a1[4];
            const int kc = k0 + 2 * tg;
            a0[0] = *reinterpret_cast<const uint32_t*>(A + (wm + g)      * AH_STRIDE + kc);
            a0[1] = *reinterpret_cast<const uint32_t*>(A + (wm + g + 8)  * AH_STRIDE + kc);
            a0[2] = *reinterpret_cast<const uint32_t*>(A + (wm + g)      * AH_STRIDE + kc + 8);
            a0[3] = *reinterpret_cast<const uint32_t*>(A + (wm + g + 8)  * AH_STRIDE + kc + 8);
            a1[0] = *reinterpret_cast<const uint32_t*>(A + (wm + 16 + g)     * AH_STRIDE + kc);
            a1[1] = *reinterpret_cast<const uint32_t*>(A + (wm + 16 + g + 8) * AH_STRIDE + kc);
            a1[2] = *reinterpret_cast<const uint32_t*>(A + (wm + 16 + g)     * AH_STRIDE + kc + 8);
            a1[3] = *reinterpret_cast<const uint32_t*>(A + (wm + 16 + g + 8) * AH_STRIDE + kc + 8);
#pragma unroll
            for (int bx = 0; bx < 4; bx++) {
                const int nrow = wn + bx * 8 + g;
                uint32_t b0 = *reinterpret_cast<const uint32_t*>(B + nrow * AH_STRIDE + kc);
                uint32_t b1 = *reinterpret_cast<const uint32_t*>(B + nrow * AH_STRIDE + kc + 8);
                mma_f16(acc[0][bx], a0, b0, b1);
                mma_f16(acc[1][bx], a1, b0, b1);
            }
        }
        __syncthreads();
    }

    // fused tdot write (only one y-tile writes; reduce over the 4 owning lanes)
    if (which) {
        tacc += __shfl_xor_sync(0xFFFFFFFFu, tacc, 1);
        tacc += __shfl_xor_sync(0xFFFFFFFFu, tacc, 2);
        if (blockIdx.y == 0 && (t & 3) == 0 && tile_m + ar < M)
            g_tdot[tile_m + ar] = tacc + g_ct;
    }

    // ---- epilogue ----
    const int slot = blockIdx.y * 4 + (wid & 3);
#pragma unroll
    for (int am = 0; am < 2; am++) {
        const int m0 = tile_m + wm + am * 16 + g;
        const int m1 = m0 + 8;
        float d0 = 0.f, d1 = 0.f;
#pragma unroll
        for (int bx = 0; bx < 4; bx++) {
            const int col = tile_n + wn + bx * 8 + tg * 2;
            const float bi0 = bias[col], bi1 = bias[col + 1];
            float v00 = acc[am][bx][0] + bi0, v01 = acc[am][bx][1] + bi1;
            float v10 = acc[am][bx][2] + bi0, v11 = acc[am][bx][3] + bi1;
            if (which == 0) {
                const float wa0 = Wa[col], wa1 = Wa[col + 1];
                d0 = fmaf(v00, wa0, fmaf(v01, wa1, d0));
                d1 = fmaf(v10, wa0, fmaf(v11, wa1, d1));
                if (m0 < M)
                    *reinterpret_cast<float2*>(g_src_proj + (long)m0 * OUT_DIM + col) =
                        make_float2(v00, v01);
                if (m1 < M)
                    *reinterpret_cast<float2*>(g_src_proj + (long)m1 * OUT_DIM + col) =
                        make_float2(v10, v11);
            } else {
                if (m0 < M)
                    *reinterpret_cast<__half2*>(g_vals_h + (long)m0 * OUT_DIM + col) =
                        __floats2half2_rn(v00, v01);
                if (m1 < M)
                    *reinterpret_cast<__half2*>(g_vals_h + (long)m1 * OUT_DIM + col) =
                        __floats2half2_rn(v10, v11);
            }
        }
        if (which == 0) {
            d0 += __shfl_xor_sync(0xFFFFFFFFu, d0, 1);
            d0 += __shfl_xor_sync(0xFFFFFFFFu, d0, 2);
            d1 += __shfl_xor_sync(0xFFFFFFFFu, d1, 1);
            d1 += __shfl_xor_sync(0xFFFFFFFFu, d1, 2);
            if (tg == 0) {
                if (m0 < M) g_sdot_part[slot][m0] = d0;
                if (m1 < M) g_sdot_part[slot][m1] = d1;
            }
        }
    }
}

// ---------------- softmax: warp per source node ------------------------------
__global__ void k_softmax(const void* __restrict__ tidp,
                          const float* __restrict__ ba, int Ns) {
    const int w = (blockIdx.x * blockDim.x + threadIdx.x) >> 5;
    const int lane = threadIdx.x & 31;
    if (w >= Ns) return;
    const int is64 = g_idx64;
    const int s0 = g_seg_start[w], s1 = g_seg_end[w];

    float p = 0.f;
    if (lane < 16) p = g_sdot_part[lane & 7][w * 2 + (lane >> 3)];
    p += __shfl_xor_sync(0xFFFFFFFFu, p, 1);
    p += __shfl_xor_sync(0xFFFFFFFFu, p, 2);
    p += __shfl_xor_sync(0xFFFFFFFFu, p, 4);
    const float sd0 = __shfl_sync(0xFFFFFFFFu, p, 0) + ba[0];
    const float sd1 = __shfl_sync(0xFFFFFFFFu, p, 8) + ba[0];

    float d0 = 0.f, d1 = 0.f;
    for (int e = s0 + lane; e < s1; e += 32) {
        int tg = IDX(tidp, e, is64);
        float sc0 = sd0 + g_tdot[tg * 2 + 0];
        float sc1 = sd1 + g_tdot[tg * 2 + 1];
        sc0 = (sc0 >= 0.f) ? sc0 : SLOPE * sc0;
        sc1 = (sc1 >= 0.f) ? sc1 : SLOPE * sc1;
        sc0 = fminf(2.f, fmaxf(-2.f, sc0));
        sc1 = fminf(2.f, fmaxf(-2.f, sc1));
        float e0 = expf(sc0), e1 = expf(sc1);
        g_ex[e * 2 + 0] = e0;
        g_ex[e * 2 + 1] = e1;
        d0 += e0;
        d1 += e1;
    }
#pragma unroll
    for (int st = 16; st; st >>= 1) {
        d0 += __shfl_xor_sync(0xFFFFFFFFu, d0, st);
        d1 += __shfl_xor_sync(0xFFFFFFFFu, d1, st);
    }
    if (lane == 0) {
        g_denom[w * 2 + 0] = d0;
        g_denom[w * 2 + 1] = d1;
    }
}

// ---------------- aggregation: 2 nodes / block, half2 loads, inline pack ----
__global__ __launch_bounds__(512) void k_agg(const void* __restrict__ sidp,
                                             const void* __restrict__ tidp,
                                             float* __restrict__ out, int Ns) {
    __shared__ float2 ws[2][16];
    __shared__ int rs[2][16];
    const int t = threadIdx.x;
    const int sub = t >> 8;
    const int rest = t & 255;
    const int b = rest >> 7;
    const int o2 = rest & 127;
    const int is64 = g_idx64;

    const int n = blockIdx.x * 2 + sub;
    const bool valid = (n < Ns);
    const int n0 = blockIdx.x * 2;
    const int n1 = min(n0 + 1, Ns - 1);
    const int cmax = max(g_seg_end[n0] - g_seg_start[n0],
                         g_seg_end[n1] - g_seg_start[n1]);
    const int s0 = valid ? g_seg_start[n] : 0;
    const int s1 = valid ? g_seg_end[n] : 0;

    const long outbase = ((long)n * BATCH + b) * OUT_DIM + 2 * o2;
    float2 acc = valid ? *reinterpret_cast<const float2*>(g_src_proj + outbase)
                       : make_float2(0.f, 0.f);
    float2 acc2 = make_float2(0.f, 0.f);

    for (int base = 0; base < cmax; base += 16) {
        if (rest < 16) {
            int e = s0 + base + rest;
            if (e < s1) {
                int j = IDX(tidp, e, is64);
                int sj = IDX(sidp, j, is64);
                ws[sub][rest] = make_float2(g_ex[j * 2 + 0] / g_denom[sj * 2 + 0],
                                            g_ex[j * 2 + 1] / g_denom[sj * 2 + 1]);
                rs[sub][rest] = IDX(tidp, j, is64);
            } else {
                ws[sub][rest] = make_float2(0.f, 0.f);
                rs[sub][rest] = 0;
            }
        }
        __syncthreads();
        const int lim = min(16, s1 - s0 - base);
        if (lim == 16) {
#pragma unroll
            for (int i = 0; i < 16; i += 2) {
                float2 wA2 = ws[sub][i];
                float2 wB2 = ws[sub][i + 1];
                float wA = b ? wA2.y : wA2.x;
                float wB = b ? wB2.y : wB2.x;
                __half2 hA = *reinterpret_cast<const __half2*>(
                    g_vals_h + (((long)rs[sub][i] << 1) + b) * OUT_DIM + 2 * o2);
                __half2 hB = *reinterpret_cast<const __half2*>(
                    g_vals_h + (((long)rs[sub][i + 1] << 1) + b) * OUT_DIM + 2 * o2);
                float2 vA = __half22float2(hA);
                float2 vB = __half22float2(hB);
                acc.x  = fmaf(wA, vA.x, acc.x);
                acc.y  = fmaf(wA, vA.y, acc.y);
                acc2.x = fmaf(wB, vB.x, acc2.x);
                acc2.y = fmaf(wB, vB.y, acc2.y);
            }
        } else {
            for (int i = 0; i < lim; i++) {
                float2 w2 = ws[sub][i];
                float w = b ? w2.y : w2.x;
                __half2 h = *reinterpret_cast<const __half2*>(
                    g_vals_h + (((long)rs[sub][i] << 1) + b) * OUT_DIM + 2 * o2);
                float2 v = __half22float2(h);
                acc.x = fmaf(w, v.x, acc.x);
                acc.y = fmaf(w, v.y, acc.y);
            }
        }
        __syncthreads();
    }
    if (valid) {
        acc.x += acc2.x;
        acc.y += acc2.y;
        *reinterpret_cast<float2*>(out + outbase) = acc;
    }
}

extern "C" void kernel_launch(void* const* d_in, const int* in_sizes, int n_in,
                              void* d_out, int out_size) {
    const float* nodes = (const float*)d_in[0];
    const float* Ws    = (const float*)d_in[1];
    const float* bs    = (const float*)d_in[2];
    const float* Wt    = (const float*)d_in[3];
    const float* bt    = (const float*)d_in[4];
    const float* Wv    = (const float*)d_in[5];
    const float* bv    = (const float*)d_in[6];
    const float* Wa    = (const float*)d_in[7];
    const float* ba    = (const float*)d_in[8];
    const void* usrc   = d_in[9];
    const void* utgt   = d_in[10];
    const void* sidp   = d_in[11];
    const void* tidp   = d_in[12];

    const int Ns = in_sizes[9];
    const int Nt = in_sizes[10];
    const int E  = in_sizes[11];
    const int ntot = in_sizes[0];
    float* out = (float*)d_out;

    static int smem_set = 0;
    if (!smem_set) {
        cudaFuncSetAttribute(k_gemm_mma, cudaFuncAttributeMaxDynamicSharedMemorySize,
                             SMH_BYTES);
        smem_set = 1;
    }

    const int Ms = Ns * BATCH;
    const int Mt = Nt * BATCH;
    const int NC = (ntot + 2047) / 2048;
    const int NE = (E + 255) / 256;

    k_prep<<<33 + NC + 128 + NE, 256>>>(usrc, Wt, bt, Wa, nodes, Ws, Wv, sidp,
                                        ntot, NC, E);

    const int Mmax = (Ms > Mt) ? Ms : Mt;
    dim3 gg((Mmax + 127) / 128, OUT_DIM / 128, 2);
    k_gemm_mma<<<gg, 512, SMH_BYTES>>>(usrc, utgt, bs, bv, Wa, Ms, Mt);

    k_softmax<<<(Ns * 32 + 255) / 256, 256>>>(tidp, ba, Ns);

    k_agg<<<(Ns + 1) / 2, 512>>>(sidp, tidp, out, Ns);
}

// round 14
// speedup vs baseline: 1.8282x; 1.1953x over previous
#include <cuda_runtime.h>
#include <cuda_fp16.h>
#include <math.h>
#include <stdint.h>

#define IN_DIM 256
#define OUT_DIM 256
#define BATCH 2
#define MAXN 10240
#define MAXE 163840
#define SLOPE 0.2f

// ---------------- scratch (static device globals; no allocation) ----------
static __device__ float  g_src_proj[MAXN * BATCH * OUT_DIM];    // 20 MB
static __device__ __half g_vals_h[MAXN * BATCH * OUT_DIM];      // 10 MB
static __device__ __half g_nodes_h[MAXN * BATCH * IN_DIM];      // 10 MB
static __device__ __half g_WhT[2 * IN_DIM * OUT_DIM];           // W^T fp16
static __device__ float  g_sdot_part[8][MAXN * BATCH];
static __device__ float  g_tdot[MAXN * BATCH];
static __device__ float  g_denom[MAXN * BATCH];
static __device__ float  g_ex[MAXE * BATCH];
static __device__ int    g_seg_start[MAXN];
static __device__ int    g_seg_end[MAXN];
static __device__ float  g_wta[IN_DIM];
static __device__ float  g_ct;
static __device__ int    g_idx64;

// ---------------- index dtype handling -------------------------------------
__device__ __forceinline__ int IDX(const void* p, int i, int is64) {
    if (is64) return (int)(((const long long*)p)[i]);
    return ((const int*)p)[i];
}

// ---------------- fused prep: detect + ct + wta + fp16 conv + seg bounds ----
__global__ void k_prep(const void* __restrict__ usrc,
                       const float* __restrict__ Wt, const float* __restrict__ bt,
                       const float* __restrict__ Wa,
                       const float* __restrict__ nodes,
                       const float* __restrict__ Ws, const float* __restrict__ Wv,
                       const void* __restrict__ sidp,
                       int ntot, int NC, int E) {
    const int bid = blockIdx.x;
    const int t = threadIdx.x;
    if (bid == 0) {
        if (t == 0) {
            const int* p = (const int*)usrc;
            g_idx64 = (p[1] == 0 && p[3] == 0) ? 1 : 0;
        }
        __shared__ float red[256];
        red[t] = bt[t] * Wa[OUT_DIM + t];
        __syncthreads();
        for (int st = 128; st > 0; st >>= 1) {
            if (t < st) red[t] += red[t + st];
            __syncthreads();
        }
        if (t == 0) g_ct = red[0];
    } else if (bid < 33) {
        const int k = (bid - 1) * 8 + (t >> 5);
        const int lane = t & 31;
        const float* wrow = Wt + (long)k * OUT_DIM;
        float s = 0.f;
#pragma unroll
        for (int o = lane; o < OUT_DIM; o += 32) s = fmaf(wrow[o], Wa[OUT_DIM + o], s);
#pragma unroll
        for (int st = 16; st; st >>= 1) s += __shfl_xor_sync(0xFFFFFFFFu, s, st);
        if (lane == 0) g_wta[k] = s;
    } else if (bid < 33 + NC) {
        long idx = (long)(bid - 33) * 2048 + t * 8;
        if (idx + 8 <= ntot) {
            float4 v0 = *reinterpret_cast<const float4*>(nodes + idx);
            float4 v1 = *reinterpret_cast<const float4*>(nodes + idx + 4);
            __half2 h0 = __floats2half2_rn(v0.x, v0.y);
            __half2 h1 = __floats2half2_rn(v0.z, v0.w);
            __half2 h2 = __floats2half2_rn(v1.x, v1.y);
            __half2 h3 = __floats2half2_rn(v1.z, v1.w);
            uint4 o;
            o.x = *reinterpret_cast<uint32_t*>(&h0);
            o.y = *reinterpret_cast<uint32_t*>(&h1);
            o.z = *reinterpret_cast<uint32_t*>(&h2);
            o.w = *reinterpret_cast<uint32_t*>(&h3);
            *reinterpret_cast<uint4*>(g_nodes_h + idx) = o;
        }
    } else if (bid < 33 + NC + 128) {
        const int j = bid - 33 - NC;          // 0..127
        const int which = j >> 6;
        const float* __restrict__ W = which ? Wv : Ws;
        const int n = (j & 63) * 4 + (t >> 6);
        const int k = (t & 63) * 4;
        __half* dst = g_WhT + (long)which * IN_DIM * OUT_DIM + (long)n * IN_DIM + k;
#pragma unroll
        for (int q = 0; q < 4; q++)
            dst[q] = __float2half_rn(W[(long)(k + q) * OUT_DIM + n]);
    } else {
        const int e = (bid - 33 - NC - 128) * 256 + t;
        if (e < E) {
            const int* p = (const int*)usrc;
            const int my64 = (p[1] == 0 && p[3] == 0) ? 1 : 0;
            const int s = IDX(sidp, e, my64);
            if (e == 0 || IDX(sidp, e - 1, my64) != s) g_seg_start[s] = e;
            if (e == E - 1 || IDX(sidp, e + 1, my64) != s) g_seg_end[s] = e + 1;
        }
    }
}

// ---------------- fp16 mma.sync gathered GEMM (3-stage, tdot fused) ---------
#define AH_STRIDE 40
#define AH_HALVES (128 * AH_STRIDE)
#define NSTAGE 3
#define SMH_BYTES (2 * NSTAGE * AH_HALVES * 2)   // 61440 B

__device__ __forceinline__ uint32_t smem_u32(const void* p) {
    uint32_t a;
    asm("{ .reg .u64 t; cvta.to.shared.u64 t, %1; cvt.u32.u64 %0, t; }" : "=r"(a) : "l"(p));
    return a;
}
#define CP_ASYNC16(smaddr, gptr) \
    asm volatile("cp.async.ca.shared.global [%0], [%1], 16;" :: "r"(smaddr), "l"(gptr))
#define CP_COMMIT() asm volatile("cp.async.commit_group;" ::: "memory")
#define CP_WAIT2()  asm volatile("cp.async.wait_group 2;" ::: "memory")
#define CP_WAIT1()  asm volatile("cp.async.wait_group 1;" ::: "memory")
#define CP_WAIT0()  asm volatile("cp.async.wait_group 0;" ::: "memory")

__device__ __forceinline__ void mma_f16(float* c, const uint32_t* a, uint32_t b0, uint32_t b1) {
    asm volatile(
        "mma.sync.aligned.m16n8k16.row.col.f32.f16.f16.f32 "
        "{%0,%1,%2,%3}, {%4,%5,%6,%7}, {%8,%9}, {%0,%1,%2,%3};"
        : "+f"(c[0]), "+f"(c[1]), "+f"(c[2]), "+f"(c[3])
        : "r"(a[0]), "r"(a[1]), "r"(a[2]), "r"(a[3]), "r"(b0), "r"(b1));
}

__global__ __launch_bounds__(512, 2) void k_gemm_mma(
    const void* __restrict__ usrc, const void* __restrict__ utgt,
    const float* __restrict__ bs, const float* __restrict__ bv,
    const float* __restrict__ Wa, int Ms, int Mt)
{
    extern __shared__ __half smh[];
    const int which = blockIdx.z;
    const void* __restrict__ uidx = which ? utgt : usrc;
    const float* __restrict__ bias = which ? bv : bs;
    const int M = which ? Mt : Ms;

    const int t = threadIdx.x;
    const int tile_m = blockIdx.x * 128;
    const int tile_n = blockIdx.y * 128;
    if (tile_m >= M) return;
    const int is64 = g_idx64;

    const int ar = t >> 2;
    const int ak = (t & 3) * 8;
    const int mclamp = min(tile_m + ar, M - 1);
    const long gath = (long)IDX(uidx, mclamp >> 1, is64) * BATCH + (mclamp & 1);
    const __half* __restrict__ aptr = g_nodes_h + gath * IN_DIM + ak;
    const __half* __restrict__ bptr =
        g_WhT + (long)which * IN_DIM * OUT_DIM + (long)(tile_n + ar) * IN_DIM + ak;

    const uint32_t sb = smem_u32(smh);
    const uint32_t a_sm = sb + (ar * AH_STRIDE + ak) * 2;
    const uint32_t b_sm = a_sm + NSTAGE * AH_HALVES * 2;

    const int wid = t >> 5, lane = t & 31;
    const int g = lane >> 2, tg = lane & 3;
    const int wm = (wid >> 2) * 32;
    const int wn = (wid & 3) * 32;

    float acc[2][4][4];
#pragma unroll
    for (int i = 0; i < 2; i++)
#pragma unroll
        for (int j = 0; j < 4; j++)
#pragma unroll
            for (int q = 0; q < 4; q++) acc[i][j][q] = 0.f;

    CP_ASYNC16(a_sm, aptr);
    CP_ASYNC16(b_sm, bptr);
    CP_COMMIT();
    CP_ASYNC16(a_sm + AH_HALVES * 2, aptr + 32);
    CP_ASYNC16(b_sm + AH_HALVES * 2, bptr + 32);
    CP_COMMIT();

    float tacc = 0.f;

    for (int c = 0; c < 8; c++) {
        const int buf = c % 3;
        if (c < 6) {
            const int kb = (c + 2) * 32;
            const uint32_t off = ((c + 2) % 3) * (AH_HALVES * 2);
            CP_ASYNC16(a_sm + off, aptr + kb);
            CP_ASYNC16(b_sm + off, bptr + kb);
            CP_COMMIT();
            CP_WAIT2();
        } else if (c == 6) {
            CP_WAIT1();
        } else {
            CP_WAIT0();
        }
        __syncthreads();

        const __half* __restrict__ A = smh + buf * AH_HALVES;
        const __half* __restrict__ B = smh + (NSTAGE + buf) * AH_HALVES;

        if (which) {
            const __half* ap = A + ar * AH_STRIDE + ak;
            const float* wp = g_wta + c * 32 + ak;
#pragma unroll
            for (int j = 0; j < 8; j++)
                tacc = fmaf(__half2float(ap[j]), wp[j], tacc);
        }

#pragma unroll
        for (int k0 = 0; k0 < 32; k0 += 16) {
            uint32_t a0[4], a1[4];
            const int kc = k0 + 2 * tg;
            a0[0] = *reinterpret_cast<const uint32_t*>(A + (wm + g)      * AH_STRIDE + kc);
            a0[1] = *reinterpret_cast<const uint32_t*>(A + (wm + g + 8)  * AH_STRIDE + kc);
            a0[2] = *reinterpret_cast<const uint32_t*>(A + (wm + g)      * AH_STRIDE + kc + 8);
            a0[3] = *reinterpret_cast<const uint32_t*>(A + (wm + g + 8)  * AH_STRIDE + kc + 8);
            a1[0] = *reinterpret_cast<const uint32_t*>(A + (wm + 16 + g)     * AH_STRIDE + kc);
            a1[1] = *reinterpret_cast<const uint32_t*>(A + (wm + 16 + g + 8) * AH_STRIDE + kc);
            a1[2] = *reinterpret_cast<const uint32_t*>(A + (wm + 16 + g)     * AH_STRIDE + kc + 8);
            a1[3] = *reinterpret_cast<const uint32_t*>(A + (wm + 16 + g + 8) * AH_STRIDE + kc + 8);
#pragma unroll
            for (int bx = 0; bx < 4; bx++) {
                const int nrow = wn + bx * 8 + g;
                uint32_t b0 = *reinterpret_cast<const uint32_t*>(B + nrow * AH_STRIDE + kc);
                uint32_t b1 = *reinterpret_cast<const uint32_t*>(B + nrow * AH_STRIDE + kc + 8);
                mma_f16(acc[0][bx], a0, b0, b1);
                mma_f16(acc[1][bx], a1, b0, b1);
            }
        }
        __syncthreads();
    }

    if (which) {
        tacc += __shfl_xor_sync(0xFFFFFFFFu, tacc, 1);
        tacc += __shfl_xor_sync(0xFFFFFFFFu, tacc, 2);
        if (blockIdx.y == 0 && (t & 3) == 0 && tile_m + ar < M)
            g_tdot[tile_m + ar] = tacc + g_ct;
    }

    // ---- epilogue ----
    const int slot = blockIdx.y * 4 + (wid & 3);
#pragma unroll
    for (int am = 0; am < 2; am++) {
        const int m0 = tile_m + wm + am * 16 + g;
        const int m1 = m0 + 8;
        float d0 = 0.f, d1 = 0.f;
#pragma unroll
        for (int bx = 0; bx < 4; bx++) {
            const int col = tile_n + wn + bx * 8 + tg * 2;
            const float bi0 = bias[col], bi1 = bias[col + 1];
            float v00 = acc[am][bx][0] + bi0, v01 = acc[am][bx][1] + bi1;
            float v10 = acc[am][bx][2] + bi0, v11 = acc[am][bx][3] + bi1;
            if (which == 0) {
                const float wa0 = Wa[col], wa1 = Wa[col + 1];
                d0 = fmaf(v00, wa0, fmaf(v01, wa1, d0));
                d1 = fmaf(v10, wa0, fmaf(v11, wa1, d1));
                if (m0 < M)
                    *reinterpret_cast<float2*>(g_src_proj + (long)m0 * OUT_DIM + col) =
                        make_float2(v00, v01);
                if (m1 < M)
                    *reinterpret_cast<float2*>(g_src_proj + (long)m1 * OUT_DIM + col) =
                        make_float2(v10, v11);
            } else {
                if (m0 < M)
                    *reinterpret_cast<__half2*>(g_vals_h + (long)m0 * OUT_DIM + col) =
                        __floats2half2_rn(v00, v01);
                if (m1 < M)
                    *reinterpret_cast<__half2*>(g_vals_h + (long)m1 * OUT_DIM + col) =
                        __floats2half2_rn(v10, v11);
            }
        }
        if (which == 0) {
            d0 += __shfl_xor_sync(0xFFFFFFFFu, d0, 1);
            d0 += __shfl_xor_sync(0xFFFFFFFFu, d0, 2);
            d1 += __shfl_xor_sync(0xFFFFFFFFu, d1, 1);
            d1 += __shfl_xor_sync(0xFFFFFFFFu, d1, 2);
            if (tg == 0) {
                if (m0 < M) g_sdot_part[slot][m0] = d0;
                if (m1 < M) g_sdot_part[slot][m1] = d1;
            }
        }
    }
}

// ---------------- softmax: warp per source node ------------------------------
__global__ void k_softmax(const void* __restrict__ tidp,
                          const float* __restrict__ ba, int Ns) {
    const int w = (blockIdx.x * blockDim.x + threadIdx.x) >> 5;
    const int lane = threadIdx.x & 31;
    if (w >= Ns) return;
    const int is64 = g_idx64;
    const int s0 = g_seg_start[w], s1 = g_seg_end[w];

    float p = 0.f;
    if (lane < 16) p = g_sdot_part[lane & 7][w * 2 + (lane >> 3)];
    p += __shfl_xor_sync(0xFFFFFFFFu, p, 1);
    p += __shfl_xor_sync(0xFFFFFFFFu, p, 2);
    p += __shfl_xor_sync(0xFFFFFFFFu, p, 4);
    const float sd0 = __shfl_sync(0xFFFFFFFFu, p, 0) + ba[0];
    const float sd1 = __shfl_sync(0xFFFFFFFFu, p, 8) + ba[0];

    float d0 = 0.f, d1 = 0.f;
    for (int e = s0 + lane; e < s1; e += 32) {
        int tg = IDX(tidp, e, is64);
        float sc0 = sd0 + g_tdot[tg * 2 + 0];
        float sc1 = sd1 + g_tdot[tg * 2 + 1];
        sc0 = (sc0 >= 0.f) ? sc0 : SLOPE * sc0;
        sc1 = (sc1 >= 0.f) ? sc1 : SLOPE * sc1;
        sc0 = fminf(2.f, fmaxf(-2.f, sc0));
        sc1 = fminf(2.f, fmaxf(-2.f, sc1));
        float e0 = expf(sc0), e1 = expf(sc1);
        g_ex[e * 2 + 0] = e0;
        g_ex[e * 2 + 1] = e1;
        d0 += e0;
        d1 += e1;
    }
#pragma unroll
    for (int st = 16; st; st >>= 1) {
        d0 += __shfl_xor_sync(0xFFFFFFFFu, d0, st);
        d1 += __shfl_xor_sync(0xFFFFFFFFu, d1, st);
    }
    if (lane == 0) {
        g_denom[w * 2 + 0] = d0;
        g_denom[w * 2 + 1] = d1;
    }
}

// ---------------- aggregation: 8 nodes / block, uint4 loads, byte offsets ---
// thread: sub = t>>6 (node), b = (t>>5)&1, o8 = t&31 (8-half col group)
__global__ __launch_bounds__(512) void k_agg(const void* __restrict__ sidp,
                                             const void* __restrict__ tidp,
                                             float* __restrict__ out, int Ns) {
    __shared__ float2 ws[8][16];
    __shared__ int ro[8][16];        // row byte offsets into g_vals_h
    __shared__ int cnts[8];
    const int t = threadIdx.x;
    const int sub = t >> 6;
    const int rest = t & 63;
    const int b = rest >> 5;
    const int o8 = rest & 31;
    const int is64 = g_idx64;

    const int n = blockIdx.x * 8 + sub;
    const bool valid = (n < Ns);
    const int s0 = valid ? g_seg_start[n] : 0;
    const int s1 = valid ? g_seg_end[n] : 0;
    if (rest == 0) cnts[sub] = s1 - s0;
    __syncthreads();
    int cmax = cnts[0];
#pragma unroll
    for (int i = 1; i < 8; i++) cmax = max(cmax, cnts[i]);

    const long outbase = ((long)n * BATCH + b) * OUT_DIM + o8 * 8;
    float acc[8];
    if (valid) {
        float4 i0 = *reinterpret_cast<const float4*>(g_src_proj + outbase);
        float4 i1 = *reinterpret_cast<const float4*>(g_src_proj + outbase + 4);
        acc[0] = i0.x; acc[1] = i0.y; acc[2] = i0.z; acc[3] = i0.w;
        acc[4] = i1.x; acc[5] = i1.y; acc[6] = i1.z; acc[7] = i1.w;
    } else {
#pragma unroll
        for (int i = 0; i < 8; i++) acc[i] = 0.f;
    }

    // per-thread constant byte offset within a row-pair: (b*256 + o8*8) halves
    const char* __restrict__ basep =
        reinterpret_cast<const char*>(g_vals_h) + ((b << 8) + (o8 << 3)) * 2;

    for (int base = 0; base < cmax; base += 16) {
        if (t < 128) {
            const int ss = t >> 4, ii = t & 15;
            const int ns = blockIdx.x * 8 + ss;
            if (ns < Ns) {
                int e = g_seg_start[ns] + base + ii;
                if (e < g_seg_end[ns]) {
                    int j = IDX(tidp, e, is64);          // faithful bug
                    int sj = IDX(sidp, j, is64);
                    ws[ss][ii] = make_float2(g_ex[j * 2 + 0] / g_denom[sj * 2 + 0],
                                             g_ex[j * 2 + 1] / g_denom[sj * 2 + 1]);
                    ro[ss][ii] = IDX(tidp, j, is64) * (BATCH * OUT_DIM * 2);
                } else {
                    ws[ss][ii] = make_float2(0.f, 0.f);
                    ro[ss][ii] = 0;
                }
            }
        }
        __syncthreads();
        const int lim = min(16, s1 - s0 - base);
        if (lim == 16) {
#pragma unroll
            for (int i = 0; i < 16; i++) {
                const float2 w2 = ws[sub][i];
                const float w = b ? w2.y : w2.x;
                uint4 h = *reinterpret_cast<const uint4*>(basep + ro[sub][i]);
                float2 v0 = __half22float2(*reinterpret_cast<__half2*>(&h.x));
                float2 v1 = __half22float2(*reinterpret_cast<__half2*>(&h.y));
                float2 v2 = __half22float2(*reinterpret_cast<__half2*>(&h.z));
                float2 v3 = __half22float2(*reinterpret_cast<__half2*>(&h.w));
                acc[0] = fmaf(w, v0.x, acc[0]);
                acc[1] = fmaf(w, v0.y, acc[1]);
                acc[2] = fmaf(w, v1.x, acc[2]);
                acc[3] = fmaf(w, v1.y, acc[3]);
                acc[4] = fmaf(w, v2.x, acc[4]);
                acc[5] = fmaf(w, v2.y, acc[5]);
                acc[6] = fmaf(w, v3.x, acc[6]);
                acc[7] = fmaf(w, v3.y, acc[7]);
            }
        } else if (lim > 0) {
            for (int i = 0; i < lim; i++) {
                const float2 w2 = ws[sub][i];
                const float w = b ? w2.y : w2.x;
                uint4 h = *reinterpret_cast<const uint4*>(basep + ro[sub][i]);
                float2 v0 = __half22float2(*reinterpret_cast<__half2*>(&h.x));
                float2 v1 = __half22float2(*reinterpret_cast<__half2*>(&h.y));
                float2 v2 = __half22float2(*reinterpret_cast<__half2*>(&h.z));
                float2 v3 = __half22float2(*reinterpret_cast<__half2*>(&h.w));
                acc[0] = fmaf(w, v0.x, acc[0]);
                acc[1] = fmaf(w, v0.y, acc[1]);
                acc[2] = fmaf(w, v1.x, acc[2]);
                acc[3] = fmaf(w, v1.y, acc[3]);
                acc[4] = fmaf(w, v2.x, acc[4]);
                acc[5] = fmaf(w, v2.y, acc[5]);
                acc[6] = fmaf(w, v3.x, acc[6]);
                acc[7] = fmaf(w, v3.y, acc[7]);
            }
        }
        __syncthreads();
    }

    if (valid) {
        float4 o0 = make_float4(acc[0], acc[1], acc[2], acc[3]);
        float4 o1 = make_float4(acc[4], acc[5], acc[6], acc[7]);
        *reinterpret_cast<float4*>(out + outbase) = o0;
        *reinterpret_cast<float4*>(out + outbase + 4) = o1;
    }
}

extern "C" void kernel_launch(void* const* d_in, const int* in_sizes, int n_in,
                              void* d_out, int out_size) {
    const float* nodes = (const float*)d_in[0];
    const float* Ws    = (const float*)d_in[1];
    const float* bs    = (const float*)d_in[2];
    const float* Wt    = (const float*)d_in[3];
    const float* bt    = (const float*)d_in[4];
    const float* Wv    = (const float*)d_in[5];
    const float* bv    = (const float*)d_in[6];
    const float* Wa    = (const float*)d_in[7];
    const float* ba    = (const float*)d_in[8];
    const void* usrc   = d_in[9];
    const void* utgt   = d_in[10];
    const void* sidp   = d_in[11];
    const void* tidp   = d_in[12];

    const int Ns = in_sizes[9];
    const int Nt = in_sizes[10];
    const int E  = in_sizes[11];
    const int ntot = in_sizes[0];
    float* out = (float*)d_out;

    static int smem_set = 0;
    if (!smem_set) {
        cudaFuncSetAttribute(k_gemm_mma, cudaFuncAttributeMaxDynamicSharedMemorySize,
                             SMH_BYTES);
        smem_set = 1;
    }

    const int Ms = Ns * BATCH;
    const int Mt = Nt * BATCH;
    const int NC = (ntot + 2047) / 2048;
    const int NE = (E + 255) / 256;

    k_prep<<<33 + NC + 128 + NE, 256>>>(usrc, Wt, bt, Wa, nodes, Ws, Wv, sidp,
                                        ntot, NC, E);

    const int Mmax = (Ms > Mt) ? Ms : Mt;
    dim3 gg((Mmax + 127) / 128, OUT_DIM / 128, 2);
    k_gemm_mma<<<gg, 512, SMH_BYTES>>>(usrc, utgt, bs, bv, Wa, Ms, Mt);

    k_softmax<<<(Ns * 32 + 255) / 256, 256>>>(tidp, ba, Ns);

    k_agg<<<(Ns + 7) / 8, 512>>>(sidp, tidp, out, Ns);
}